// round 7
// baseline (speedup 1.0000x reference)
#include <cuda_runtime.h>
#include <math.h>

#define NN 50000
#define NE 600000
#define NG 128
#define CDIM 128
#define M3 384
#define CAT 1152
#define EPSB 1e-5f

// ---------------- static scratch (no allocations allowed) ----------------
__device__ float d_neigh[(size_t)NN * CDIM];
__device__ float d_X[(size_t)NN * CDIM];
__device__ float d_H1[(size_t)NN * CDIM];
__device__ float d_H2[(size_t)NN * CDIM];
__device__ float d_Hm[(size_t)NN * M3];
__device__ float d_stX[2 * CDIM];
__device__ float d_scX[CDIM];
__device__ float d_shX[CDIM];
__device__ float d_gsum[NG * M3];
__device__ float d_gsq[NG * M3];
__device__ float d_gmax[NG * M3];
__device__ float d_gmin[NG * M3];
__device__ int   d_gcnt[NG];
__device__ float d_Hcat[NG * CAT];
__device__ float d_Hbn[NG * CAT];
__device__ float d_h1[NG * 768];
__device__ float d_h2[NG * 384];

// ---------------- tf32 helpers ----------------
__device__ __forceinline__ unsigned f2tf32(float v) {
    unsigned r;
    asm("cvt.rna.tf32.f32 %0, %1;" : "=r"(r) : "f"(v));
    return r;
}
__device__ __forceinline__ void mma_tf32(float* c, const unsigned* a, const unsigned* b) {
    asm volatile(
        "mma.sync.aligned.m16n8k8.row.col.f32.tf32.tf32.f32 "
        "{%0,%1,%2,%3}, {%4,%5,%6,%7}, {%8,%9}, {%0,%1,%2,%3};"
        : "+f"(c[0]), "+f"(c[1]), "+f"(c[2]), "+f"(c[3])
        : "r"(a[0]), "r"(a[1]), "r"(a[2]), "r"(a[3]), "r"(b[0]), "r"(b[1]));
}

// ---------------- zero scratch used by atomics / stats ----------------
__global__ void zero_all_k() {
    size_t i = (size_t)blockIdx.x * blockDim.x + threadIdx.x;
    d_neigh[i] = 0.f;
    d_H1[i] = 0.f;
    d_H2[i] = 0.f;
    if (i < 2 * CDIM) d_stX[i] = 0.f;
}

// ---------------- edge scatter: dst[sidx[e]] += src[gidx[e]] ----------------
// one warp per edge; optional per-channel affine (sc/sh) applied to gathered value
__global__ void scatter_add_k(const float* __restrict__ src, float* __restrict__ dst,
                              const int* __restrict__ gidx, const int* __restrict__ sidx,
                              const float* __restrict__ sc, const float* __restrict__ sh) {
    long t = (long)blockIdx.x * blockDim.x + threadIdx.x;
    int e = (int)(t >> 5);
    if (e >= NE) return;
    int q = (int)(t & 31);
    int g = __ldg(gidx + e);
    int s = __ldg(sidx + e);
    float4 v = __ldg((const float4*)src + (size_t)g * 32 + q);
    if (sc) {
        float4 s4 = __ldg((const float4*)sc + q);
        float4 h4 = __ldg((const float4*)sh + q);
        v.x = fmaf(v.x, s4.x, h4.x);
        v.y = fmaf(v.y, s4.y, h4.y);
        v.z = fmaf(v.z, s4.z, h4.z);
        v.w = fmaf(v.w, s4.w, h4.w);
    }
    float4* p = (float4*)dst + (size_t)s * 32 + q;
    asm volatile("red.global.add.v4.f32 [%0], {%1,%2,%3,%4};"
                 :: "l"(p), "f"(v.x), "f"(v.y), "f"(v.z), "f"(v.w)
                 : "memory");
}

// ================= tf32 tensor-core GEMM core (R5 synchronous version) =================
// Block tile 128(M) x 128(N), K=128 per input, up to 3 (A_i, W_i) pairs summed.
// 256 threads = 8 warps (4 row x 2 col); warp tile 32x64.
// Optional per-input channel affine on A (BN fusion).
__device__ __forceinline__ void gemm_core(
    const float* const* Ap, const float* const* Wp,
    const float* const* scp, const float* const* shp, int nIn, int ldw,
    const float* __restrict__ bias, float* __restrict__ Cp, int ldc,
    int r0, int cbase, unsigned (*As)[36], unsigned (*Ws)[36]) {
    const int tx = threadIdx.x;
    const int lane = tx & 31;
    const int warp = tx >> 5;
    const int wr = (warp & 3) * 32;
    const int wc = (warp >> 2) * 64;
    const int g = lane >> 2;
    const int t4 = lane & 3;

    float acc[2][8][4];
#pragma unroll
    for (int mi = 0; mi < 2; mi++)
#pragma unroll
        for (int ni = 0; ni < 8; ni++)
#pragma unroll
            for (int j = 0; j < 4; j++) acc[mi][ni][j] = 0.f;

    for (int i = 0; i < nIn; ++i) {
        const float* A = Ap[i];
        const float* W = Wp[i];
        const float* sc = scp[i];
        const float* sh = shp[i];
        for (int kb = 0; kb < 128; kb += 32) {
            __syncthreads();
#pragma unroll
            for (int it = 0; it < 4; ++it) {
                int s = tx + it * 256;     // 0..1023
                int rr = s >> 3;           // 0..127
                int kq = (s & 7) * 4;      // 0..28
                float4 va = make_float4(0.f, 0.f, 0.f, 0.f);
                if (r0 + rr < NN)
                    va = __ldg((const float4*)(A + (size_t)(r0 + rr) * CDIM + kb + kq));
                if (sc) {
                    float4 s4 = __ldg((const float4*)(sc + kb + kq));
                    float4 h4 = __ldg((const float4*)(sh + kb + kq));
                    va.x = fmaf(va.x, s4.x, h4.x);
                    va.y = fmaf(va.y, s4.y, h4.y);
                    va.z = fmaf(va.z, s4.z, h4.z);
                    va.w = fmaf(va.w, s4.w, h4.w);
                }
                As[rr][kq + 0] = f2tf32(va.x); As[rr][kq + 1] = f2tf32(va.y);
                As[rr][kq + 2] = f2tf32(va.z); As[rr][kq + 3] = f2tf32(va.w);
                float4 vw = __ldg((const float4*)(W + (size_t)rr * ldw + kb + kq));
                Ws[rr][kq + 0] = f2tf32(vw.x); Ws[rr][kq + 1] = f2tf32(vw.y);
                Ws[rr][kq + 2] = f2tf32(vw.z); Ws[rr][kq + 3] = f2tf32(vw.w);
            }
            __syncthreads();
#pragma unroll
            for (int kk = 0; kk < 32; kk += 8) {
                unsigned a[2][4], b[8][2];
#pragma unroll
                for (int mi = 0; mi < 2; mi++) {
                    int r = wr + mi * 16;
                    a[mi][0] = As[r + g][kk + t4];
                    a[mi][1] = As[r + g + 8][kk + t4];
                    a[mi][2] = As[r + g][kk + t4 + 4];
                    a[mi][3] = As[r + g + 8][kk + t4 + 4];
                }
#pragma unroll
                for (int ni = 0; ni < 8; ni++) {
                    int n = wc + ni * 8 + g;
                    b[ni][0] = Ws[n][kk + t4];
                    b[ni][1] = Ws[n][kk + t4 + 4];
                }
#pragma unroll
                for (int mi = 0; mi < 2; mi++)
#pragma unroll
                    for (int ni = 0; ni < 8; ni++)
                        mma_tf32(acc[mi][ni], a[mi], b[ni]);
            }
        }
    }
    // epilogue: add bias, write
#pragma unroll
    for (int mi = 0; mi < 2; mi++) {
        int r1 = r0 + wr + mi * 16 + g;
        int r2 = r1 + 8;
#pragma unroll
        for (int ni = 0; ni < 8; ni++) {
            int cc = wc + ni * 8 + 2 * t4;
            float b0 = bias[cc], b1 = bias[cc + 1];
            if (r1 < NN) {
                Cp[(size_t)r1 * ldc + cbase + cc] = acc[mi][ni][0] + b0;
                Cp[(size_t)r1 * ldc + cbase + cc + 1] = acc[mi][ni][1] + b1;
            }
            if (r2 < NN) {
                Cp[(size_t)r2 * ldc + cbase + cc] = acc[mi][ni][2] + b0;
                Cp[(size_t)r2 * ldc + cbase + cc + 1] = acc[mi][ni][3] + b1;
            }
        }
    }
}

// X = neigh @ w_rel^T + x @ w_root^T + b_rel
__global__ void __launch_bounds__(256, 1) gemm_x_k(
    const float* __restrict__ A0, const float* __restrict__ A1,
    const float* __restrict__ W0, const float* __restrict__ W1,
    const float* __restrict__ bias, float* __restrict__ Cp) {
    __shared__ unsigned As[128][36];
    __shared__ unsigned Ws[128][36];
    const float* Ap[3] = {A0, A1, nullptr};
    const float* Wp[3] = {W0, W1, nullptr};
    const float* Zn[3] = {nullptr, nullptr, nullptr};
    gemm_core(Ap, Wp, Zn, Zn, 2, 128, bias, Cp, 128, blockIdx.x * 128, 0, As, Ws);
}

// Hm strips: strip j uses inputs [BN(X),H1,H2][0..j], W block row j
__global__ void __launch_bounds__(256, 1) gemm_hm_k(
    const float* __restrict__ lin_w, const float* __restrict__ lin_b) {
    __shared__ unsigned As[128][36];
    __shared__ unsigned Ws[128][36];
    int j = blockIdx.y;
    const float* Ap[3] = {d_X, d_H1, d_H2};
    const float* Wp[3];
    for (int i = 0; i < 3; i++)
        Wp[i] = lin_w + (size_t)(j * 128) * M3 + i * 128;
    const float* Sc[3] = {d_scX, nullptr, nullptr};
    const float* Sh[3] = {d_shX, nullptr, nullptr};
    gemm_core(Ap, Wp, Sc, Sh, j + 1, M3, lin_b + j * 128, d_Hm, M3,
              blockIdx.x * 128, j * 128, As, Ws);
}

// ---------------- per-column sum/sumsq over NN rows (X only) ----------------
__global__ void stats2_k(const float* __restrict__ A, int ncol, float* __restrict__ st,
                         int rows_per_blk) {
    __shared__ float sm[384 * 8];
    int n4 = ncol >> 2;
    int c4 = threadIdx.x % n4;
    int rl = threadIdx.x / n4;
    int rstep = blockDim.x / n4;
    int r0 = blockIdx.x * rows_per_blk;
    int rend = min(r0 + rows_per_blk, NN);
    float4 s = make_float4(0, 0, 0, 0), q = make_float4(0, 0, 0, 0);
    for (int r = r0 + rl; r < rend; r += rstep) {
        float4 v = __ldg((const float4*)(A + (size_t)r * ncol) + c4);
        s.x += v.x; s.y += v.y; s.z += v.z; s.w += v.w;
        q.x += v.x * v.x; q.y += v.y * v.y; q.z += v.z * v.z; q.w += v.w * v.w;
    }
    float* my = sm + threadIdx.x * 8;
    my[0] = s.x; my[1] = s.y; my[2] = s.z; my[3] = s.w;
    my[4] = q.x; my[5] = q.y; my[6] = q.z; my[7] = q.w;
    __syncthreads();
    if (threadIdx.x < (unsigned)n4) {
        float acc[8];
#pragma unroll
        for (int k = 0; k < 8; k++) acc[k] = 0.f;
        for (int j = 0; j < rstep; j++) {
            float* p = sm + (c4 + j * n4) * 8;
#pragma unroll
            for (int k = 0; k < 8; k++) acc[k] += p[k];
        }
#pragma unroll
        for (int k = 0; k < 4; k++) {
            atomicAdd(st + c4 * 4 + k, acc[k]);
            atomicAdd(st + ncol + c4 * 4 + k, acc[4 + k]);
        }
    }
}

// ---------------- finalize BN(X): stats -> per-channel scale/shift ----------------
__global__ void finalize_bnX_k(const float* __restrict__ gw, const float* __restrict__ gb) {
    int c = threadIdx.x;  // 128
    float mean = d_stX[c] * (1.f / NN);
    float var = d_stX[CDIM + c] * (1.f / NN) - mean * mean;
    float sc = gw[c] * rsqrtf(var + EPSB);
    d_scX[c] = sc;
    d_shX[c] = gb[c] - mean * sc;
}

// ---------------- per-graph raw pooling over Hm: sum/sumsq/max/min ----------------
// One block per graph; 384 threads = 96 col-quads x 4 row-lanes; float4 loads.
__global__ void pool_raw_k(const int* __restrict__ batch) {
    __shared__ float sm[384 * 16];
    int gph = blockIdx.x;
    int tx = threadIdx.x;
    int c4 = tx % 96;
    int rl = tx / 96;
    int lo = 0, hi = NN;
    while (lo < hi) { int m = (lo + hi) >> 1; if (batch[m] < gph) lo = m + 1; else hi = m; }
    int start = lo;
    lo = start; hi = NN;
    while (lo < hi) { int m = (lo + hi) >> 1; if (batch[m] < gph + 1) lo = m + 1; else hi = m; }
    int end = lo;

    float4 s = make_float4(0, 0, 0, 0), q = make_float4(0, 0, 0, 0);
    float4 mx = make_float4(-INFINITY, -INFINITY, -INFINITY, -INFINITY);
    float4 mn = make_float4(INFINITY, INFINITY, INFINITY, INFINITY);
    for (int r = start + rl; r < end; r += 4) {
        float4 v = __ldg((const float4*)(d_Hm + (size_t)r * M3) + c4);
        s.x += v.x; s.y += v.y; s.z += v.z; s.w += v.w;
        q.x += v.x * v.x; q.y += v.y * v.y; q.z += v.z * v.z; q.w += v.w * v.w;
        mx.x = fmaxf(mx.x, v.x); mx.y = fmaxf(mx.y, v.y);
        mx.z = fmaxf(mx.z, v.z); mx.w = fmaxf(mx.w, v.w);
        mn.x = fminf(mn.x, v.x); mn.y = fminf(mn.y, v.y);
        mn.z = fminf(mn.z, v.z); mn.w = fminf(mn.w, v.w);
    }
    float* my = sm + tx * 16;
    my[0] = s.x; my[1] = s.y; my[2] = s.z; my[3] = s.w;
    my[4] = q.x; my[5] = q.y; my[6] = q.z; my[7] = q.w;
    my[8] = mx.x; my[9] = mx.y; my[10] = mx.z; my[11] = mx.w;
    my[12] = mn.x; my[13] = mn.y; my[14] = mn.z; my[15] = mn.w;
    __syncthreads();
    if (rl == 0) {  // tx < 96
        float a[16];
#pragma unroll
        for (int k = 0; k < 16; k++) a[k] = my[k];
        for (int j = 1; j < 4; j++) {
            float* p = sm + (tx + j * 96) * 16;
#pragma unroll
            for (int k = 0; k < 4; k++) {
                a[k] += p[k];
                a[4 + k] += p[4 + k];
                a[8 + k] = fmaxf(a[8 + k], p[8 + k]);
                a[12 + k] = fminf(a[12 + k], p[12 + k]);
            }
        }
#pragma unroll
        for (int k = 0; k < 4; k++) {
            int col = c4 * 4 + k;
            d_gsum[gph * M3 + col] = a[k];
            d_gsq[gph * M3 + col] = a[4 + k];
            d_gmax[gph * M3 + col] = a[8 + k];
            d_gmin[gph * M3 + col] = a[12 + k];
        }
    }
    if (tx == 0) d_gcnt[gph] = end - start;
}

// ---------------- finalize pooling: bnh BN stats from per-graph sums, emit Hcat ----------------
__global__ void finalize_pool_k(const float* __restrict__ gw, const float* __restrict__ gb) {
    int c = blockIdx.x * 128 + threadIdx.x;  // 0..383
    float ts = 0.f, tq = 0.f;
    for (int g2 = 0; g2 < NG; g2++) {
        ts += d_gsum[g2 * M3 + c];
        tq += d_gsq[g2 * M3 + c];
    }
    float mean = ts * (1.f / NN);
    float var = tq * (1.f / NN) - mean * mean;
    float sc = gw[c] * rsqrtf(var + EPSB);
    float sh = gb[c] - mean * sc;
    for (int g2 = 0; g2 < NG; g2++) {
        int cnt = d_gcnt[g2];
        float add = sc * d_gsum[g2 * M3 + c] + sh * (float)cnt;
        float avg = (cnt > 0) ? add / (float)cnt : 0.f;
        float mxv = 0.f;
        if (cnt > 0)
            mxv = (sc >= 0.f) ? fmaf(sc, d_gmax[g2 * M3 + c], sh)
                              : fmaf(sc, d_gmin[g2 * M3 + c], sh);
        d_Hcat[(size_t)g2 * CAT + c] = avg;
        d_Hcat[(size_t)g2 * CAT + 384 + c] = add;
        d_Hcat[(size_t)g2 * CAT + 768 + c] = mxv;
    }
}

// ---------------- BN over graphs (128 rows x 1152 cols) ----------------
__global__ void bn_graphs_k(const float* __restrict__ gw, const float* __restrict__ gb) {
    int c = blockIdx.x * blockDim.x + threadIdx.x;
    if (c >= CAT) return;
    float s = 0.f, ss = 0.f;
    for (int r = 0; r < NG; r++) { float v = d_Hcat[r * CAT + c]; s += v; ss += v * v; }
    float mean = s * (1.f / NG);
    float var = ss * (1.f / NG) - mean * mean;
    float sc = gw[c] * rsqrtf(var + EPSB);
    float sh = gb[c] - mean * sc;
    for (int r = 0; r < NG; r++) d_Hbn[r * CAT + c] = fmaf(d_Hcat[r * CAT + c], sc, sh);
}

// ---------------- small dense layer ----------------
__global__ void mlp_k(const float* __restrict__ A, int Kd,
                      const float* __restrict__ W, const float* __restrict__ bias,
                      float* __restrict__ out, int Od, int do_relu) {
    extern __shared__ float sA[];  // 8*Kd
    int g0 = blockIdx.y * 8;
    for (int idx = threadIdx.x; idx < 8 * Kd; idx += blockDim.x)
        sA[idx] = A[(size_t)(g0 + idx / Kd) * Kd + (idx % Kd)];
    __syncthreads();
    int o = blockIdx.x * blockDim.x + threadIdx.x;
    float bb = bias[o];
    float acc[8];
#pragma unroll
    for (int j = 0; j < 8; j++) acc[j] = bb;
    const float* wr = W + (size_t)o * Kd;
    for (int k = 0; k < Kd; k++) {
        float w = wr[k];
#pragma unroll
        for (int j = 0; j < 8; j++) acc[j] = fmaf(w, sA[j * Kd + k], acc[j]);
    }
#pragma unroll
    for (int j = 0; j < 8; j++) {
        float v = acc[j];
        if (do_relu) v = fmaxf(v, 0.f);
        out[(size_t)(g0 + j) * Od + o] = v;
    }
}

// ---------------- final layer + log_softmax ----------------
__global__ void final_k(const float* __restrict__ w3, const float* __restrict__ b3,
                        float* __restrict__ out) {
    int g = threadIdx.x;
    if (g >= NG) return;
    float l0 = b3[0], l1 = b3[1];
    const float* h = d_h2 + (size_t)g * 384;
    for (int k = 0; k < 384; k++) {
        float v = h[k];
        l0 = fmaf(v, w3[k], l0);
        l1 = fmaf(v, w3[384 + k], l1);
    }
    float m = fmaxf(l0, l1);
    float lse = m + logf(expf(l0 - m) + expf(l1 - m));
    out[g * 2 + 0] = l0 - lse;
    out[g * 2 + 1] = l1 - lse;
}

extern "C" void kernel_launch(void* const* d_in, const int* in_sizes, int n_in,
                              void* d_out, int out_size) {
    const float* x      = (const float*)d_in[0];
    const int*   ei     = (const int*)d_in[1];
    const int*   batch  = (const int*)d_in[2];
    const float* w_rel  = (const float*)d_in[4];
    const float* b_rel  = (const float*)d_in[5];
    const float* w_root = (const float*)d_in[6];
    const float* n0g    = (const float*)d_in[7];
    const float* n0b    = (const float*)d_in[8];
    const float* lin_w  = (const float*)d_in[9];
    const float* lin_b  = (const float*)d_in[10];
    const float* bnh_g  = (const float*)d_in[11];
    const float* bnh_b  = (const float*)d_in[12];
    const float* bno_g  = (const float*)d_in[13];
    const float* bno_b  = (const float*)d_in[14];
    const float* w1     = (const float*)d_in[15];
    const float* b1     = (const float*)d_in[16];
    const float* w2     = (const float*)d_in[17];
    const float* b2     = (const float*)d_in[18];
    const float* w3     = (const float*)d_in[19];
    const float* b3     = (const float*)d_in[20];
    float* out = (float*)d_out;
    const int* row = ei;            // edge_index[0]
    const int* col = ei + NE;       // edge_index[1]

    float *p_neigh, *p_X, *p_H1, *p_H2, *p_stX, *p_scX, *p_shX, *p_Hbn, *p_h1, *p_h2;
    cudaGetSymbolAddress((void**)&p_neigh, d_neigh);
    cudaGetSymbolAddress((void**)&p_X, d_X);
    cudaGetSymbolAddress((void**)&p_H1, d_H1);
    cudaGetSymbolAddress((void**)&p_H2, d_H2);
    cudaGetSymbolAddress((void**)&p_stX, d_stX);
    cudaGetSymbolAddress((void**)&p_scX, d_scX);
    cudaGetSymbolAddress((void**)&p_shX, d_shX);
    cudaGetSymbolAddress((void**)&p_Hbn, d_Hbn);
    cudaGetSymbolAddress((void**)&p_h1, d_h1);
    cudaGetSymbolAddress((void**)&p_h2, d_h2);

    const int ROWBLK = (NN + 127) / 128;  // 391

    zero_all_k<<<(NN * CDIM) / 256, 256>>>();
    // neigh[col] += x[row]
    scatter_add_k<<<(NE * 32) / 256, 256>>>(x, p_neigh, row, col, nullptr, nullptr);
    // X = neigh @ w_rel^T + x @ w_root^T + b_rel   (tf32, synchronous R5 core)
    gemm_x_k<<<ROWBLK, 256>>>(p_neigh, x, w_rel, w_root, b_rel, p_X);
    // BN(X) stats -> scale/shift
    stats2_k<<<400, 256>>>(p_X, 128, p_stX, 125);
    finalize_bnX_k<<<1, 128>>>(n0g, n0b);
    // H1[row] += BN(X)[col]  (affine fused into gather), H2[row] += H1[col]
    scatter_add_k<<<(NE * 32) / 256, 256>>>(p_X, p_H1, col, row, p_scX, p_shX);
    scatter_add_k<<<(NE * 32) / 256, 256>>>(p_H1, p_H2, col, row, nullptr, nullptr);
    // masked block-lower-triangular lin GEMM, 3 strips, BN(X) fused on input 0
    gemm_hm_k<<<dim3(ROWBLK, 3), 256>>>(lin_w, lin_b);
    // per-graph raw pool (single read of Hm), then bnh-BN + pooled outputs
    pool_raw_k<<<NG, 384>>>(batch);
    finalize_pool_k<<<3, 128>>>(bnh_g, bnh_b);
    bn_graphs_k<<<CAT / 128, 128>>>(bno_g, bno_b);
    mlp_k<<<dim3(768 / 128, NG / 8), 128, 8 * 1152 * sizeof(float)>>>(
        p_Hbn, 1152, w1, b1, p_h1, 768, 1);
    mlp_k<<<dim3(384 / 128, NG / 8), 128, 8 * 768 * sizeof(float)>>>(
        p_h1, 768, w2, b2, p_h2, 384, 1);
    final_k<<<1, 128>>>(w3, b3, out);
}

// round 8
// speedup vs baseline: 1.1049x; 1.1049x over previous
#include <cuda_runtime.h>
#include <math.h>

#define NN 50000
#define NE 600000
#define NG 128
#define CDIM 128
#define M3 384
#define CAT 1152
#define EPSB 1e-5f
#define SCAN_T 1024

// ---------------- static scratch (no allocations allowed) ----------------
__device__ float d_neigh[(size_t)NN * CDIM];
__device__ float d_X[(size_t)NN * CDIM];
__device__ float d_H1[(size_t)NN * CDIM];
__device__ float d_H2[(size_t)NN * CDIM];
__device__ float d_Hm[(size_t)NN * M3];
__device__ float d_stX[2 * CDIM];
__device__ float d_stH[2 * M3];
__device__ float d_scX[CDIM];
__device__ float d_shX[CDIM];
__device__ float d_Hcat[NG * CAT];
__device__ float d_Hbn[NG * CAT];
__device__ float d_h1[NG * 768];
__device__ float d_h2[NG * 384];
// CSR scratch
__device__ int d_degc[NN], d_degr[NN];
__device__ int d_offc[NN + 1], d_offr[NN + 1];
__device__ int d_curc[NN], d_curr[NN];
__device__ int d_srcc[NE];   // for dst=col passes: source node (row[e])
__device__ int d_srcr[NE];   // for dst=row passes: source node (col[e])

// ---------------- tf32 helpers ----------------
__device__ __forceinline__ unsigned f2tf32(float v) {
    unsigned r;
    asm("cvt.rna.tf32.f32 %0, %1;" : "=r"(r) : "f"(v));
    return r;
}
__device__ __forceinline__ void mma_tf32(float* c, const unsigned* a, const unsigned* b) {
    asm volatile(
        "mma.sync.aligned.m16n8k8.row.col.f32.tf32.tf32.f32 "
        "{%0,%1,%2,%3}, {%4,%5,%6,%7}, {%8,%9}, {%0,%1,%2,%3};"
        : "+f"(c[0]), "+f"(c[1]), "+f"(c[2]), "+f"(c[3])
        : "r"(a[0]), "r"(a[1]), "r"(a[2]), "r"(a[3]), "r"(b[0]), "r"(b[1]));
}

// ---------------- init: zero degrees + stats accumulators ----------------
__global__ void init_k() {
    int i = blockIdx.x * blockDim.x + threadIdx.x;
    if (i < NN) { d_degc[i] = 0; d_degr[i] = 0; }
    if (i < 2 * CDIM) d_stX[i] = 0.f;
    if (i < 2 * M3) d_stH[i] = 0.f;
}

// ---------------- degree histogram ----------------
__global__ void hist_k(const int* __restrict__ row, const int* __restrict__ col) {
    int e = blockIdx.x * blockDim.x + threadIdx.x;
    if (e >= NE) return;
    atomicAdd(&d_degc[__ldg(col + e)], 1);
    atomicAdd(&d_degr[__ldg(row + e)], 1);
}

// ---------------- exclusive scan of one degree array (single block each) ----------------
// blockIdx.x = 0: degc -> offc/curc ; 1: degr -> offr/curr
__global__ void scan_k() {
    __shared__ int sm[SCAN_T];
    const int* deg = (blockIdx.x == 0) ? d_degc : d_degr;
    int* off = (blockIdx.x == 0) ? d_offc : d_offr;
    int* cur = (blockIdx.x == 0) ? d_curc : d_curr;
    int t = threadIdx.x;
    const int CH = (NN + SCAN_T - 1) / SCAN_T;  // 49
    int b = t * CH, e = min(b + CH, NN);
    int s = 0;
    for (int i = b; i < e; i++) s += deg[i];
    sm[t] = s;
    __syncthreads();
    for (int d = 1; d < SCAN_T; d <<= 1) {
        int u = (t >= d) ? sm[t - d] : 0;
        __syncthreads();
        sm[t] += u;
        __syncthreads();
    }
    int p = (t == 0) ? 0 : sm[t - 1];
    for (int i = b; i < e; i++) {
        off[i] = p;
        cur[i] = p;
        p += deg[i];
    }
    if (t == SCAN_T - 1) off[NN] = sm[SCAN_T - 1];
}

// ---------------- fill CSR edge lists ----------------
__global__ void fill_k(const int* __restrict__ row, const int* __restrict__ col) {
    int e = blockIdx.x * blockDim.x + threadIdx.x;
    if (e >= NE) return;
    int r = __ldg(row + e), c = __ldg(col + e);
    int pc = atomicAdd(&d_curc[c], 1);
    d_srcc[pc] = r;
    int pr = atomicAdd(&d_curr[r], 1);
    d_srcr[pr] = c;
}

// ---------------- CSR gather-accumulate: dst[n] = sum_{e in CSR(n)} src[idx[e]] ----------------
// one warp per destination node; optional post-sum affine (sc*acc + sh*deg)
__global__ void spmm_csr_k(const float* __restrict__ src, float* __restrict__ dst,
                           const int* __restrict__ off, const int* __restrict__ idx,
                           const float* __restrict__ sc, const float* __restrict__ sh) {
    int node = blockIdx.x * 8 + (threadIdx.x >> 5);
    if (node >= NN) return;
    int q = threadIdx.x & 31;
    int beg = __ldg(off + node), end = __ldg(off + node + 1);
    float4 acc = make_float4(0.f, 0.f, 0.f, 0.f);
    int e = beg;
    for (; e + 1 < end; e += 2) {
        int s0 = __ldg(idx + e), s1 = __ldg(idx + e + 1);
        float4 v0 = __ldg((const float4*)src + (size_t)s0 * 32 + q);
        float4 v1 = __ldg((const float4*)src + (size_t)s1 * 32 + q);
        acc.x += v0.x + v1.x;
        acc.y += v0.y + v1.y;
        acc.z += v0.z + v1.z;
        acc.w += v0.w + v1.w;
    }
    if (e < end) {
        int s0 = __ldg(idx + e);
        float4 v0 = __ldg((const float4*)src + (size_t)s0 * 32 + q);
        acc.x += v0.x; acc.y += v0.y; acc.z += v0.z; acc.w += v0.w;
    }
    if (sc) {
        float d = (float)(end - beg);
        float4 s4 = __ldg((const float4*)sc + q);
        float4 h4 = __ldg((const float4*)sh + q);
        acc.x = fmaf(acc.x, s4.x, h4.x * d);
        acc.y = fmaf(acc.y, s4.y, h4.y * d);
        acc.z = fmaf(acc.z, s4.z, h4.z * d);
        acc.w = fmaf(acc.w, s4.w, h4.w * d);
    }
    ((float4*)dst)[(size_t)node * 32 + q] = acc;
}

// ================= tf32 tensor-core GEMM core (R5 synchronous version) =================
__device__ __forceinline__ void gemm_core(
    const float* const* Ap, const float* const* Wp,
    const float* const* scp, const float* const* shp, int nIn, int ldw,
    const float* __restrict__ bias, float* __restrict__ Cp, int ldc,
    int r0, int cbase, unsigned (*As)[36], unsigned (*Ws)[36]) {
    const int tx = threadIdx.x;
    const int lane = tx & 31;
    const int warp = tx >> 5;
    const int wr = (warp & 3) * 32;
    const int wc = (warp >> 2) * 64;
    const int g = lane >> 2;
    const int t4 = lane & 3;

    float acc[2][8][4];
#pragma unroll
    for (int mi = 0; mi < 2; mi++)
#pragma unroll
        for (int ni = 0; ni < 8; ni++)
#pragma unroll
            for (int j = 0; j < 4; j++) acc[mi][ni][j] = 0.f;

    for (int i = 0; i < nIn; ++i) {
        const float* A = Ap[i];
        const float* W = Wp[i];
        const float* sc = scp[i];
        const float* sh = shp[i];
        for (int kb = 0; kb < 128; kb += 32) {
            __syncthreads();
#pragma unroll
            for (int it = 0; it < 4; ++it) {
                int s = tx + it * 256;     // 0..1023
                int rr = s >> 3;           // 0..127
                int kq = (s & 7) * 4;      // 0..28
                float4 va = make_float4(0.f, 0.f, 0.f, 0.f);
                if (r0 + rr < NN)
                    va = __ldg((const float4*)(A + (size_t)(r0 + rr) * CDIM + kb + kq));
                if (sc) {
                    float4 s4 = __ldg((const float4*)(sc + kb + kq));
                    float4 h4 = __ldg((const float4*)(sh + kb + kq));
                    va.x = fmaf(va.x, s4.x, h4.x);
                    va.y = fmaf(va.y, s4.y, h4.y);
                    va.z = fmaf(va.z, s4.z, h4.z);
                    va.w = fmaf(va.w, s4.w, h4.w);
                }
                As[rr][kq + 0] = f2tf32(va.x); As[rr][kq + 1] = f2tf32(va.y);
                As[rr][kq + 2] = f2tf32(va.z); As[rr][kq + 3] = f2tf32(va.w);
                float4 vw = __ldg((const float4*)(W + (size_t)rr * ldw + kb + kq));
                Ws[rr][kq + 0] = f2tf32(vw.x); Ws[rr][kq + 1] = f2tf32(vw.y);
                Ws[rr][kq + 2] = f2tf32(vw.z); Ws[rr][kq + 3] = f2tf32(vw.w);
            }
            __syncthreads();
#pragma unroll
            for (int kk = 0; kk < 32; kk += 8) {
                unsigned a[2][4], b[8][2];
#pragma unroll
                for (int mi = 0; mi < 2; mi++) {
                    int r = wr + mi * 16;
                    a[mi][0] = As[r + g][kk + t4];
                    a[mi][1] = As[r + g + 8][kk + t4];
                    a[mi][2] = As[r + g][kk + t4 + 4];
                    a[mi][3] = As[r + g + 8][kk + t4 + 4];
                }
#pragma unroll
                for (int ni = 0; ni < 8; ni++) {
                    int n = wc + ni * 8 + g;
                    b[ni][0] = Ws[n][kk + t4];
                    b[ni][1] = Ws[n][kk + t4 + 4];
                }
#pragma unroll
                for (int mi = 0; mi < 2; mi++)
#pragma unroll
                    for (int ni = 0; ni < 8; ni++)
                        mma_tf32(acc[mi][ni], a[mi], b[ni]);
            }
        }
    }
#pragma unroll
    for (int mi = 0; mi < 2; mi++) {
        int r1 = r0 + wr + mi * 16 + g;
        int r2 = r1 + 8;
#pragma unroll
        for (int ni = 0; ni < 8; ni++) {
            int cc = wc + ni * 8 + 2 * t4;
            float b0 = bias[cc], b1 = bias[cc + 1];
            if (r1 < NN) {
                Cp[(size_t)r1 * ldc + cbase + cc] = acc[mi][ni][0] + b0;
                Cp[(size_t)r1 * ldc + cbase + cc + 1] = acc[mi][ni][1] + b1;
            }
            if (r2 < NN) {
                Cp[(size_t)r2 * ldc + cbase + cc] = acc[mi][ni][2] + b0;
                Cp[(size_t)r2 * ldc + cbase + cc + 1] = acc[mi][ni][3] + b1;
            }
        }
    }
}

// X = neigh @ w_rel^T + x @ w_root^T + b_rel
__global__ void __launch_bounds__(256, 1) gemm_x_k(
    const float* __restrict__ A0, const float* __restrict__ A1,
    const float* __restrict__ W0, const float* __restrict__ W1,
    const float* __restrict__ bias, float* __restrict__ Cp) {
    __shared__ unsigned As[128][36];
    __shared__ unsigned Ws[128][36];
    const float* Ap[3] = {A0, A1, nullptr};
    const float* Wp[3] = {W0, W1, nullptr};
    const float* Zn[3] = {nullptr, nullptr, nullptr};
    gemm_core(Ap, Wp, Zn, Zn, 2, 128, bias, Cp, 128, blockIdx.x * 128, 0, As, Ws);
}

// Hm strips: strip j uses inputs [BN(X),H1,H2][0..j], W block row j
__global__ void __launch_bounds__(256, 1) gemm_hm_k(
    const float* __restrict__ lin_w, const float* __restrict__ lin_b) {
    __shared__ unsigned As[128][36];
    __shared__ unsigned Ws[128][36];
    int j = blockIdx.y;
    const float* Ap[3] = {d_X, d_H1, d_H2};
    const float* Wp[3];
    for (int i = 0; i < 3; i++)
        Wp[i] = lin_w + (size_t)(j * 128) * M3 + i * 128;
    const float* Sc[3] = {d_scX, nullptr, nullptr};
    const float* Sh[3] = {d_shX, nullptr, nullptr};
    gemm_core(Ap, Wp, Sc, Sh, j + 1, M3, lin_b + j * 128, d_Hm, M3,
              blockIdx.x * 128, j * 128, As, Ws);
}

// ---------------- per-column sum/sumsq over NN rows ----------------
__global__ void stats2_k(const float* __restrict__ A, int ncol, float* __restrict__ st,
                         int rows_per_blk) {
    __shared__ float sm[384 * 8];
    int n4 = ncol >> 2;
    int c4 = threadIdx.x % n4;
    int rl = threadIdx.x / n4;
    int rstep = blockDim.x / n4;
    int r0 = blockIdx.x * rows_per_blk;
    int rend = min(r0 + rows_per_blk, NN);
    float4 s = make_float4(0, 0, 0, 0), q = make_float4(0, 0, 0, 0);
    for (int r = r0 + rl; r < rend; r += rstep) {
        float4 v = __ldg((const float4*)(A + (size_t)r * ncol) + c4);
        s.x += v.x; s.y += v.y; s.z += v.z; s.w += v.w;
        q.x += v.x * v.x; q.y += v.y * v.y; q.z += v.z * v.z; q.w += v.w * v.w;
    }
    float* my = sm + threadIdx.x * 8;
    my[0] = s.x; my[1] = s.y; my[2] = s.z; my[3] = s.w;
    my[4] = q.x; my[5] = q.y; my[6] = q.z; my[7] = q.w;
    __syncthreads();
    if (threadIdx.x < (unsigned)n4) {
        float acc[8];
#pragma unroll
        for (int k = 0; k < 8; k++) acc[k] = 0.f;
        for (int j = 0; j < rstep; j++) {
            float* p = sm + (c4 + j * n4) * 8;
#pragma unroll
            for (int k = 0; k < 8; k++) acc[k] += p[k];
        }
#pragma unroll
        for (int k = 0; k < 4; k++) {
            atomicAdd(st + c4 * 4 + k, acc[k]);
            atomicAdd(st + ncol + c4 * 4 + k, acc[4 + k]);
        }
    }
}

// ---------------- finalize BN(X): stats -> per-channel scale/shift ----------------
__global__ void finalize_bnX_k(const float* __restrict__ gw, const float* __restrict__ gb) {
    int c = threadIdx.x;  // 128
    float mean = d_stX[c] * (1.f / NN);
    float var = d_stX[CDIM + c] * (1.f / NN) - mean * mean;
    float sc = gw[c] * rsqrtf(var + EPSB);
    d_scX[c] = sc;
    d_shX[c] = gb[c] - mean * sc;
}

// ---------------- pooling (fuses bnh BatchNorm apply) ----------------
__global__ void pool_k(const int* __restrict__ batch,
                       const float* __restrict__ gw, const float* __restrict__ gb) {
    int g = blockIdx.x;
    int c = threadIdx.x;  // 384
    int lo = 0, hi = NN;
    while (lo < hi) { int mid = (lo + hi) >> 1; if (batch[mid] < g) lo = mid + 1; else hi = mid; }
    int start = lo;
    lo = start; hi = NN;
    while (lo < hi) { int mid = (lo + hi) >> 1; if (batch[mid] < g + 1) lo = mid + 1; else hi = mid; }
    int end = lo;

    float mean = d_stH[c] * (1.f / NN);
    float var = d_stH[M3 + c] * (1.f / NN) - mean * mean;
    float sc = gw[c] * rsqrtf(var + EPSB);
    float sh = gb[c] - mean * sc;

    float s = 0.f;
    float mx = -INFINITY;
    for (int r = start; r < end; ++r) {
        float v = fmaf(d_Hm[(size_t)r * M3 + c], sc, sh);
        s += v;
        mx = fmaxf(mx, v);
    }
    int cnt = end - start;
    d_Hcat[(size_t)g * CAT + c] = (cnt > 0) ? s / (float)cnt : 0.f;
    d_Hcat[(size_t)g * CAT + 384 + c] = s;
    d_Hcat[(size_t)g * CAT + 768 + c] = (cnt > 0) ? mx : 0.f;
}

// ---------------- BN over graphs (128 rows x 1152 cols) ----------------
__global__ void bn_graphs_k(const float* __restrict__ gw, const float* __restrict__ gb) {
    int c = blockIdx.x * blockDim.x + threadIdx.x;
    if (c >= CAT) return;
    float s = 0.f, ss = 0.f;
    for (int r = 0; r < NG; r++) { float v = d_Hcat[r * CAT + c]; s += v; ss += v * v; }
    float mean = s * (1.f / NG);
    float var = ss * (1.f / NG) - mean * mean;
    float sc = gw[c] * rsqrtf(var + EPSB);
    float sh = gb[c] - mean * sc;
    for (int r = 0; r < NG; r++) d_Hbn[r * CAT + c] = fmaf(d_Hcat[r * CAT + c], sc, sh);
}

// ---------------- small dense layer ----------------
__global__ void mlp_k(const float* __restrict__ A, int Kd,
                      const float* __restrict__ W, const float* __restrict__ bias,
                      float* __restrict__ out, int Od, int do_relu) {
    extern __shared__ float sA[];  // 8*Kd
    int g0 = blockIdx.y * 8;
    for (int idx = threadIdx.x; idx < 8 * Kd; idx += blockDim.x)
        sA[idx] = A[(size_t)(g0 + idx / Kd) * Kd + (idx % Kd)];
    __syncthreads();
    int o = blockIdx.x * blockDim.x + threadIdx.x;
    float bb = bias[o];
    float acc[8];
#pragma unroll
    for (int j = 0; j < 8; j++) acc[j] = bb;
    const float* wr = W + (size_t)o * Kd;
    for (int k = 0; k < Kd; k++) {
        float w = wr[k];
#pragma unroll
        for (int j = 0; j < 8; j++) acc[j] = fmaf(w, sA[j * Kd + k], acc[j]);
    }
#pragma unroll
    for (int j = 0; j < 8; j++) {
        float v = acc[j];
        if (do_relu) v = fmaxf(v, 0.f);
        out[(size_t)(g0 + j) * Od + o] = v;
    }
}

// ---------------- final layer + log_softmax ----------------
__global__ void final_k(const float* __restrict__ w3, const float* __restrict__ b3,
                        float* __restrict__ out) {
    int g = threadIdx.x;
    if (g >= NG) return;
    float l0 = b3[0], l1 = b3[1];
    const float* h = d_h2 + (size_t)g * 384;
    for (int k = 0; k < 384; k++) {
        float v = h[k];
        l0 = fmaf(v, w3[k], l0);
        l1 = fmaf(v, w3[384 + k], l1);
    }
    float m = fmaxf(l0, l1);
    float lse = m + logf(expf(l0 - m) + expf(l1 - m));
    out[g * 2 + 0] = l0 - lse;
    out[g * 2 + 1] = l1 - lse;
}

extern "C" void kernel_launch(void* const* d_in, const int* in_sizes, int n_in,
                              void* d_out, int out_size) {
    const float* x      = (const float*)d_in[0];
    const int*   ei     = (const int*)d_in[1];
    const int*   batch  = (const int*)d_in[2];
    const float* w_rel  = (const float*)d_in[4];
    const float* b_rel  = (const float*)d_in[5];
    const float* w_root = (const float*)d_in[6];
    const float* n0g    = (const float*)d_in[7];
    const float* n0b    = (const float*)d_in[8];
    const float* lin_w  = (const float*)d_in[9];
    const float* lin_b  = (const float*)d_in[10];
    const float* bnh_g  = (const float*)d_in[11];
    const float* bnh_b  = (const float*)d_in[12];
    const float* bno_g  = (const float*)d_in[13];
    const float* bno_b  = (const float*)d_in[14];
    const float* w1     = (const float*)d_in[15];
    const float* b1     = (const float*)d_in[16];
    const float* w2     = (const float*)d_in[17];
    const float* b2     = (const float*)d_in[18];
    const float* w3     = (const float*)d_in[19];
    const float* b3     = (const float*)d_in[20];
    float* out = (float*)d_out;
    const int* row = ei;            // edge_index[0]
    const int* col = ei + NE;       // edge_index[1]

    float *p_neigh, *p_X, *p_H1, *p_H2, *p_Hm, *p_stX, *p_stH, *p_scX, *p_shX;
    float *p_Hbn, *p_h1, *p_h2;
    int *p_offc, *p_offr, *p_srcc, *p_srcr;
    cudaGetSymbolAddress((void**)&p_neigh, d_neigh);
    cudaGetSymbolAddress((void**)&p_X, d_X);
    cudaGetSymbolAddress((void**)&p_H1, d_H1);
    cudaGetSymbolAddress((void**)&p_H2, d_H2);
    cudaGetSymbolAddress((void**)&p_Hm, d_Hm);
    cudaGetSymbolAddress((void**)&p_stX, d_stX);
    cudaGetSymbolAddress((void**)&p_stH, d_stH);
    cudaGetSymbolAddress((void**)&p_scX, d_scX);
    cudaGetSymbolAddress((void**)&p_shX, d_shX);
    cudaGetSymbolAddress((void**)&p_Hbn, d_Hbn);
    cudaGetSymbolAddress((void**)&p_h1, d_h1);
    cudaGetSymbolAddress((void**)&p_h2, d_h2);
    cudaGetSymbolAddress((void**)&p_offc, d_offc);
    cudaGetSymbolAddress((void**)&p_offr, d_offr);
    cudaGetSymbolAddress((void**)&p_srcc, d_srcc);
    cudaGetSymbolAddress((void**)&p_srcr, d_srcr);

    const int ROWBLK = (NN + 127) / 128;   // 391
    const int NODEBLK = (NN + 7) / 8;      // 6250

    // ---- CSR build ----
    init_k<<<(NN + 255) / 256, 256>>>();
    hist_k<<<(NE + 255) / 256, 256>>>(row, col);
    scan_k<<<2, SCAN_T>>>();
    fill_k<<<(NE + 255) / 256, 256>>>(row, col);
    // ---- neigh[n] = sum over in-edges (dst=col) of x[src] ----
    spmm_csr_k<<<NODEBLK, 256>>>(x, p_neigh, p_offc, p_srcc, nullptr, nullptr);
    // X = neigh @ w_rel^T + x @ w_root^T + b_rel
    gemm_x_k<<<ROWBLK, 256>>>(p_neigh, x, w_rel, w_root, b_rel, p_X);
    stats2_k<<<400, 256>>>(p_X, 128, p_stX, 125);
    finalize_bnX_k<<<1, 128>>>(n0g, n0b);
    // H1[n] = sum (dst=row) of BN(X)[src]; H2[n] = sum of H1[src]
    spmm_csr_k<<<NODEBLK, 256>>>(p_X, p_H1, p_offr, p_srcr, p_scX, p_shX);
    spmm_csr_k<<<NODEBLK, 256>>>(p_H1, p_H2, p_offr, p_srcr, nullptr, nullptr);
    // masked block-lower-triangular lin GEMM, 3 strips, BN(X) fused on input 0
    gemm_hm_k<<<dim3(ROWBLK, 3), 256>>>(lin_w, lin_b);
    stats2_k<<<400, 384>>>(p_Hm, 384, p_stH, 125);
    pool_k<<<NG, 384>>>(batch, bnh_g, bnh_b);
    bn_graphs_k<<<CAT / 128, 128>>>(bno_g, bno_b);
    mlp_k<<<dim3(768 / 128, NG / 8), 128, 8 * 1152 * sizeof(float)>>>(
        p_Hbn, 1152, w1, b1, p_h1, 768, 1);
    mlp_k<<<dim3(384 / 128, NG / 8), 128, 8 * 768 * sizeof(float)>>>(
        p_h1, 768, w2, b2, p_h2, 384, 1);
    final_k<<<1, 128>>>(w3, b3, out);
}

// round 11
// speedup vs baseline: 1.1333x; 1.0258x over previous
#include <cuda_runtime.h>
#include <math.h>
#include <stdint.h>

#define NN 50000
#define NE 600000
#define NG 128
#define CDIM 128
#define M3 384
#define CAT 1152
#define EPSB 1e-5f
#define SCAN_T 1024
#define AST 36                       // smem row stride (words)
#define GSMEM (4 * 128 * AST * 4)    // 2 stages x (A+W) x 128x36 words

// ---------------- static scratch (no allocations allowed) ----------------
__device__ float d_neigh[(size_t)NN * CDIM];
__device__ float d_X[(size_t)NN * CDIM];
__device__ float d_Xr[(size_t)NN * CDIM];
__device__ float d_xr[(size_t)NN * CDIM];
__device__ float d_H1[(size_t)NN * CDIM];
__device__ float d_H2[(size_t)NN * CDIM];
__device__ float d_Hm[(size_t)NN * M3];
__device__ float d_wrelt[CDIM * CDIM];
__device__ float d_wroott[CDIM * CDIM];
__device__ float d_linwt[M3 * M3];
__device__ float d_linbt[M3];
__device__ float d_stX[2 * CDIM];
__device__ float d_stH[2 * M3];
__device__ float d_scX[CDIM];
__device__ float d_shX[CDIM];
__device__ float d_Hcat[NG * CAT];
__device__ float d_Hbn[NG * CAT];
__device__ float d_h1[NG * 768];
__device__ float d_h2[NG * 384];
// CSR scratch
__device__ int d_degc[NN], d_degr[NN];
__device__ int d_offc[NN + 1], d_offr[NN + 1];
__device__ int d_curc[NN], d_curr[NN];
__device__ int d_srcc[NE];
__device__ int d_srcr[NE];

// ---------------- tf32 helpers ----------------
__device__ __forceinline__ unsigned f2tf32(float v) {
    unsigned r;
    asm("cvt.rna.tf32.f32 %0, %1;" : "=r"(r) : "f"(v));
    return r;
}
__device__ __forceinline__ float rnd_tf32(float v) { return __uint_as_float(f2tf32(v)); }
__device__ __forceinline__ void mma_tf32(float* c, const unsigned* a, const unsigned* b) {
    asm volatile(
        "mma.sync.aligned.m16n8k8.row.col.f32.tf32.tf32.f32 "
        "{%0,%1,%2,%3}, {%4,%5,%6,%7}, {%8,%9}, {%0,%1,%2,%3};"
        : "+f"(c[0]), "+f"(c[1]), "+f"(c[2]), "+f"(c[3])
        : "r"(a[0]), "r"(a[1]), "r"(a[2]), "r"(a[3]), "r"(b[0]), "r"(b[1]));
}
// ---------------- cp.async helpers ----------------
__device__ __forceinline__ void cpa16(uint32_t saddr, const void* g, int bytes) {
    asm volatile("cp.async.cg.shared.global [%0], [%1], 16, %2;"
                 :: "r"(saddr), "l"(g), "r"(bytes));
}
__device__ __forceinline__ void cpa_commit() { asm volatile("cp.async.commit_group;"); }
__device__ __forceinline__ void cpa_wait1() { asm volatile("cp.async.wait_group 1;"); }
__device__ __forceinline__ void cpa_wait0() { asm volatile("cp.async.wait_group 0;"); }

// ---------------- init: zero degrees + stats accumulators ----------------
__global__ void init_k() {
    int i = blockIdx.x * blockDim.x + threadIdx.x;
    if (i < NN) { d_degc[i] = 0; d_degr[i] = 0; }
    if (i < 2 * CDIM) d_stX[i] = 0.f;
    if (i < 2 * M3) d_stH[i] = 0.f;
}

// ---------------- degree histogram ----------------
__global__ void hist_k(const int* __restrict__ row, const int* __restrict__ col) {
    int e = blockIdx.x * blockDim.x + threadIdx.x;
    if (e >= NE) return;
    atomicAdd(&d_degc[__ldg(col + e)], 1);
    atomicAdd(&d_degr[__ldg(row + e)], 1);
}

// ---------------- exclusive scan (single block per array) ----------------
__global__ void scan_k() {
    __shared__ int sm[SCAN_T];
    const int* deg = (blockIdx.x == 0) ? d_degc : d_degr;
    int* off = (blockIdx.x == 0) ? d_offc : d_offr;
    int* cur = (blockIdx.x == 0) ? d_curc : d_curr;
    int t = threadIdx.x;
    const int CH = (NN + SCAN_T - 1) / SCAN_T;
    int b = t * CH, e = min(b + CH, NN);
    int s = 0;
    for (int i = b; i < e; i++) s += deg[i];
    sm[t] = s;
    __syncthreads();
    for (int d = 1; d < SCAN_T; d <<= 1) {
        int u = (t >= d) ? sm[t - d] : 0;
        __syncthreads();
        sm[t] += u;
        __syncthreads();
    }
    int p = (t == 0) ? 0 : sm[t - 1];
    for (int i = b; i < e; i++) {
        off[i] = p;
        cur[i] = p;
        p += deg[i];
    }
    if (t == SCAN_T - 1) off[NN] = sm[SCAN_T - 1];
}

// ---------------- fill CSR edge lists ----------------
__global__ void fill_k(const int* __restrict__ row, const int* __restrict__ col) {
    int e = blockIdx.x * blockDim.x + threadIdx.x;
    if (e >= NE) return;
    int r = __ldg(row + e), c = __ldg(col + e);
    int pc = atomicAdd(&d_curc[c], 1);
    d_srcc[pc] = r;
    int pr = atomicAdd(&d_curr[r], 1);
    d_srcr[pr] = c;
}

// ---------------- round-copy (tf32 quantize) ----------------
__global__ void round_copy_k(const float* __restrict__ src, float* __restrict__ dst, int n) {
    int i = blockIdx.x * blockDim.x + threadIdx.x;
    if (i < n) dst[i] = rnd_tf32(__ldg(src + i));
}

// ---------------- CSR gather-accumulate; stores tf32-rounded ----------------
__global__ void spmm_csr_k(const float* __restrict__ src, float* __restrict__ dst,
                           const int* __restrict__ off, const int* __restrict__ idx,
                           const float* __restrict__ sc, const float* __restrict__ sh) {
    int node = blockIdx.x * 8 + (threadIdx.x >> 5);
    if (node >= NN) return;
    int q = threadIdx.x & 31;
    int beg = __ldg(off + node), end = __ldg(off + node + 1);
    float4 acc = make_float4(0.f, 0.f, 0.f, 0.f);
    int e = beg;
    for (; e + 1 < end; e += 2) {
        int s0 = __ldg(idx + e), s1 = __ldg(idx + e + 1);
        float4 v0 = __ldg((const float4*)src + (size_t)s0 * 32 + q);
        float4 v1 = __ldg((const float4*)src + (size_t)s1 * 32 + q);
        acc.x += v0.x + v1.x;
        acc.y += v0.y + v1.y;
        acc.z += v0.z + v1.z;
        acc.w += v0.w + v1.w;
    }
    if (e < end) {
        int s0 = __ldg(idx + e);
        float4 v0 = __ldg((const float4*)src + (size_t)s0 * 32 + q);
        acc.x += v0.x; acc.y += v0.y; acc.z += v0.z; acc.w += v0.w;
    }
    if (sc) {
        float d = (float)(end - beg);
        float4 s4 = __ldg((const float4*)sc + q);
        float4 h4 = __ldg((const float4*)sh + q);
        acc.x = fmaf(acc.x, s4.x, h4.x * d);
        acc.y = fmaf(acc.y, s4.y, h4.y * d);
        acc.z = fmaf(acc.z, s4.z, h4.z * d);
        acc.w = fmaf(acc.w, s4.w, h4.w * d);
    }
    acc.x = rnd_tf32(acc.x); acc.y = rnd_tf32(acc.y);
    acc.z = rnd_tf32(acc.z); acc.w = rnd_tf32(acc.w);
    ((float4*)dst)[(size_t)node * 32 + q] = acc;
}

// ---------------- stage issue helper for async GEMM ----------------
__device__ __forceinline__ void gemm_issue_stage(
    const float* const* Ap, const float* const* Wp, int st, int ldw,
    int r0, int rrb, int kq, uint32_t sbase, int BUF) {
    const float* A = Ap[st >> 2];
    const float* W = Wp[st >> 2];
    int kb = (st & 3) * 32;
    uint32_t abase = sbase + (uint32_t)((st & 1) * BUF) * 4;
    uint32_t wbase = abase + 128 * AST * 4;
#pragma unroll
    for (int it = 0; it < 4; ++it) {
        int rr = rrb + it * 32;
        int r = r0 + rr;
        int ok = (r < NN);
        const float* ga = A + (size_t)(ok ? r : 0) * CDIM + kb + kq;
        cpa16(abase + (uint32_t)(rr * AST + kq) * 4, ga, ok ? 16 : 0);
        cpa16(wbase + (uint32_t)(rr * AST + kq) * 4, W + (size_t)rr * ldw + kb + kq, 16);
    }
    cpa_commit();
}

// ================= tf32 GEMM core, cp.async double-buffered =================
// All A/W operands are pre-rounded tf32 bits; MMA consumes raw smem words.
// smem layout (words): [A0 | W0 | A1 | W1], each 128*AST.
__device__ __forceinline__ void gemm_core_async(
    const float* const* Ap, const float* const* Wp, int nIn, int ldw,
    const float* __restrict__ bias, float* __restrict__ Cp, int ldc,
    int r0, int cbase, float* __restrict__ C2p, unsigned* smemu) {
    const int tx = threadIdx.x;
    const int lane = tx & 31;
    const int warp = tx >> 5;
    const int wr = (warp & 3) * 32;
    const int wc = (warp >> 2) * 64;
    const int g = lane >> 2;
    const int t4 = lane & 3;
    const int rrb = tx >> 3;        // 0..31
    const int kq = (tx & 7) * 4;    // 0..28
    const uint32_t sbase = (uint32_t)__cvta_generic_to_shared(smemu);
    const int BUF = 2 * 128 * AST;  // words per stage (A+W)

    float acc[2][8][4];
#pragma unroll
    for (int mi = 0; mi < 2; mi++)
#pragma unroll
        for (int ni = 0; ni < 8; ni++)
#pragma unroll
            for (int j = 0; j < 4; j++) acc[mi][ni][j] = 0.f;

    const int nSteps = nIn * 4;

    gemm_issue_stage(Ap, Wp, 0, ldw, r0, rrb, kq, sbase, BUF);
    for (int st = 0; st < nSteps; ++st) {
        if (st + 1 < nSteps) {
            gemm_issue_stage(Ap, Wp, st + 1, ldw, r0, rrb, kq, sbase, BUF);
            cpa_wait1();
        } else {
            cpa_wait0();
        }
        __syncthreads();
        const unsigned* Ab = smemu + (st & 1) * BUF;
        const unsigned* Wb = Ab + 128 * AST;
#pragma unroll
        for (int kk = 0; kk < 32; kk += 8) {
            unsigned a[2][4], b[8][2];
#pragma unroll
            for (int mi = 0; mi < 2; mi++) {
                int r = wr + mi * 16;
                a[mi][0] = Ab[(r + g) * AST + kk + t4];
                a[mi][1] = Ab[(r + g + 8) * AST + kk + t4];
                a[mi][2] = Ab[(r + g) * AST + kk + t4 + 4];
                a[mi][3] = Ab[(r + g + 8) * AST + kk + t4 + 4];
            }
#pragma unroll
            for (int ni = 0; ni < 8; ni++) {
                int n = wc + ni * 8 + g;
                b[ni][0] = Wb[n * AST + kk + t4];
                b[ni][1] = Wb[n * AST + kk + t4 + 4];
            }
#pragma unroll
            for (int mi = 0; mi < 2; mi++)
#pragma unroll
                for (int ni = 0; ni < 8; ni++)
                    mma_tf32(acc[mi][ni], a[mi], b[ni]);
        }
        __syncthreads();
    }

    // epilogue: bias, write (optionally also tf32-rounded secondary)
#pragma unroll
    for (int mi = 0; mi < 2; mi++) {
        int r1 = r0 + wr + mi * 16 + g;
        int r2 = r1 + 8;
#pragma unroll
        for (int ni = 0; ni < 8; ni++) {
            int cc = wc + ni * 8 + 2 * t4;
            float b0 = bias[cc], b1 = bias[cc + 1];
            if (r1 < NN) {
                float v0 = acc[mi][ni][0] + b0, v1 = acc[mi][ni][1] + b1;
                Cp[(size_t)r1 * ldc + cbase + cc] = v0;
                Cp[(size_t)r1 * ldc + cbase + cc + 1] = v1;
                if (C2p) {
                    C2p[(size_t)r1 * ldc + cbase + cc] = rnd_tf32(v0);
                    C2p[(size_t)r1 * ldc + cbase + cc + 1] = rnd_tf32(v1);
                }
            }
            if (r2 < NN) {
                float v2 = acc[mi][ni][2] + b0, v3 = acc[mi][ni][3] + b1;
                Cp[(size_t)r2 * ldc + cbase + cc] = v2;
                Cp[(size_t)r2 * ldc + cbase + cc + 1] = v3;
                if (C2p) {
                    C2p[(size_t)r2 * ldc + cbase + cc] = rnd_tf32(v2);
                    C2p[(size_t)r2 * ldc + cbase + cc + 1] = rnd_tf32(v3);
                }
            }
        }
    }
}

// X = neigh @ w_rel^T + xr @ w_root^T + b_rel ; also writes Xr (tf32-rounded)
__global__ void __launch_bounds__(256, 1) gemm_x_k(const float* __restrict__ bias) {
    extern __shared__ unsigned smemu[];
    const float* Ap[3] = {d_neigh, d_xr, nullptr};
    const float* Wp[3] = {d_wrelt, d_wroott, nullptr};
    gemm_core_async(Ap, Wp, 2, 128, bias, d_X, 128, blockIdx.x * 128, 0, d_Xr, smemu);
}

// Hm strips with BN(X) folded into transformed weights/bias
__global__ void __launch_bounds__(256, 1) gemm_hm_k() {
    extern __shared__ unsigned smemu[];
    int j = blockIdx.y;
    const float* Ap[3] = {d_Xr, d_H1, d_H2};
    const float* Wp[3];
    for (int i = 0; i < 3; i++)
        Wp[i] = d_linwt + (size_t)(j * 128) * M3 + i * 128;
    gemm_core_async(Ap, Wp, j + 1, M3, d_linbt + j * 128, d_Hm, M3,
                    blockIdx.x * 128, j * 128, nullptr, smemu);
}

// ---------------- per-column sum/sumsq over NN rows ----------------
__global__ void stats2_k(const float* __restrict__ A, int ncol, float* __restrict__ st,
                         int rows_per_blk) {
    __shared__ float sm[384 * 8];
    int n4 = ncol >> 2;
    int c4 = threadIdx.x % n4;
    int rl = threadIdx.x / n4;
    int rstep = blockDim.x / n4;
    int r0 = blockIdx.x * rows_per_blk;
    int rend = min(r0 + rows_per_blk, NN);
    float4 s = make_float4(0, 0, 0, 0), q = make_float4(0, 0, 0, 0);
    for (int r = r0 + rl; r < rend; r += rstep) {
        float4 v = __ldg((const float4*)(A + (size_t)r * ncol) + c4);
        s.x += v.x; s.y += v.y; s.z += v.z; s.w += v.w;
        q.x += v.x * v.x; q.y += v.y * v.y; q.z += v.z * v.z; q.w += v.w * v.w;
    }
    float* my = sm + threadIdx.x * 8;
    my[0] = s.x; my[1] = s.y; my[2] = s.z; my[3] = s.w;
    my[4] = q.x; my[5] = q.y; my[6] = q.z; my[7] = q.w;
    __syncthreads();
    if (threadIdx.x < (unsigned)n4) {
        float acc[8];
#pragma unroll
        for (int k = 0; k < 8; k++) acc[k] = 0.f;
        for (int j = 0; j < rstep; j++) {
            float* p = sm + (c4 + j * n4) * 8;
#pragma unroll
            for (int k = 0; k < 8; k++) acc[k] += p[k];
        }
#pragma unroll
        for (int k = 0; k < 4; k++) {
            atomicAdd(st + c4 * 4 + k, acc[k]);
            atomicAdd(st + ncol + c4 * 4 + k, acc[4 + k]);
        }
    }
}

// ---------------- finalize BN(X): stats -> per-channel scale/shift ----------------
__global__ void finalize_bnX_k(const float* __restrict__ gw, const float* __restrict__ gb) {
    int c = threadIdx.x;  // 128
    float mean = d_stX[c] * (1.f / NN);
    float var = d_stX[CDIM + c] * (1.f / NN) - mean * mean;
    float sc = gw[c] * rsqrtf(var + EPSB);
    d_scX[c] = sc;
    d_shX[c] = gb[c] - mean * sc;
}

// ---------------- fold BN(X) into lin weights/bias; tf32-round all of lin_w ----------------
__global__ void lin_transform_k(const float* __restrict__ lin_w, const float* __restrict__ lin_b) {
    __shared__ float red[128];
    int o = blockIdx.x;   // 0..383
    int t = threadIdx.x;  // 0..127
    const float* wrow = lin_w + (size_t)o * M3;
    float w0 = wrow[t];
    d_linwt[(size_t)o * M3 + t] = rnd_tf32(w0 * d_scX[t]);
    d_linwt[(size_t)o * M3 + 128 + t] = rnd_tf32(wrow[128 + t]);
    d_linwt[(size_t)o * M3 + 256 + t] = rnd_tf32(wrow[256 + t]);
    red[t] = d_shX[t] * w0;
    __syncthreads();
    for (int s2 = 64; s2 > 0; s2 >>= 1) {
        if (t < s2) red[t] += red[t + s2];
        __syncthreads();
    }
    if (t == 0) d_linbt[o] = lin_b[o] + red[0];
}

// ---------------- pooling (fuses bnh BatchNorm apply) ----------------
__global__ void pool_k(const int* __restrict__ batch,
                       const float* __restrict__ gw, const float* __restrict__ gb) {
    int g = blockIdx.x;
    int c = threadIdx.x;  // 384
    int lo = 0, hi = NN;
    while (lo < hi) { int mid = (lo + hi) >> 1; if (batch[mid] < g) lo = mid + 1; else hi = mid; }
    int start = lo;
    lo = start; hi = NN;
    while (lo < hi) { int mid = (lo + hi) >> 1; if (batch[mid] < g + 1) lo = mid + 1; else hi = mid; }
    int end = lo;

    float mean = d_stH[c] * (1.f / NN);
    float var = d_stH[M3 + c] * (1.f / NN) - mean * mean;
    float sc = gw[c] * rsqrtf(var + EPSB);
    float sh = gb[c] - mean * sc;

    float s = 0.f;
    float mx = -INFINITY;
    for (int r = start; r < end; ++r) {
        float v = fmaf(d_Hm[(size_t)r * M3 + c], sc, sh);
        s += v;
        mx = fmaxf(mx, v);
    }
    int cnt = end - start;
    d_Hcat[(size_t)g * CAT + c] = (cnt > 0) ? s / (float)cnt : 0.f;
    d_Hcat[(size_t)g * CAT + 384 + c] = s;
    d_Hcat[(size_t)g * CAT + 768 + c] = (cnt > 0) ? mx : 0.f;
}

// ---------------- BN over graphs ----------------
__global__ void bn_graphs_k(const float* __restrict__ gw, const float* __restrict__ gb) {
    int c = blockIdx.x * blockDim.x + threadIdx.x;
    if (c >= CAT) return;
    float s = 0.f, ss = 0.f;
    for (int r = 0; r < NG; r++) { float v = d_Hcat[r * CAT + c]; s += v; ss += v * v; }
    float mean = s * (1.f / NG);
    float var = ss * (1.f / NG) - mean * mean;
    float sc = gw[c] * rsqrtf(var + EPSB);
    float sh = gb[c] - mean * sc;
    for (int r = 0; r < NG; r++) d_Hbn[r * CAT + c] = fmaf(d_Hcat[r * CAT + c], sc, sh);
}

// ---------------- small dense layer ----------------
__global__ void mlp_k(const float* __restrict__ A, int Kd,
                      const float* __restrict__ W, const float* __restrict__ bias,
                      float* __restrict__ out, int Od, int do_relu) {
    extern __shared__ float sA[];
    int g0 = blockIdx.y * 8;
    for (int idx = threadIdx.x; idx < 8 * Kd; idx += blockDim.x)
        sA[idx] = A[(size_t)(g0 + idx / Kd) * Kd + (idx % Kd)];
    __syncthreads();
    int o = blockIdx.x * blockDim.x + threadIdx.x;
    float bb = bias[o];
    float acc[8];
#pragma unroll
    for (int j = 0; j < 8; j++) acc[j] = bb;
    const float* wr = W + (size_t)o * Kd;
    for (int k = 0; k < Kd; k++) {
        float w = wr[k];
#pragma unroll
        for (int j = 0; j < 8; j++) acc[j] = fmaf(w, sA[j * Kd + k], acc[j]);
    }
#pragma unroll
    for (int j = 0; j < 8; j++) {
        float v = acc[j];
        if (do_relu) v = fmaxf(v, 0.f);
        out[(size_t)(g0 + j) * Od + o] = v;
    }
}

// ---------------- final layer + log_softmax ----------------
__global__ void final_k(const float* __restrict__ w3, const float* __restrict__ b3,
                        float* __restrict__ out) {
    int g = threadIdx.x;
    if (g >= NG) return;
    float l0 = b3[0], l1 = b3[1];
    const float* h = d_h2 + (size_t)g * 384;
    for (int k = 0; k < 384; k++) {
        float v = h[k];
        l0 = fmaf(v, w3[k], l0);
        l1 = fmaf(v, w3[384 + k], l1);
    }
    float m = fmaxf(l0, l1);
    float lse = m + logf(expf(l0 - m) + expf(l1 - m));
    out[g * 2 + 0] = l0 - lse;
    out[g * 2 + 1] = l1 - lse;
}

extern "C" void kernel_launch(void* const* d_in, const int* in_sizes, int n_in,
                              void* d_out, int out_size) {
    const float* x      = (const float*)d_in[0];
    const int*   ei     = (const int*)d_in[1];
    const int*   batch  = (const int*)d_in[2];
    const float* w_rel  = (const float*)d_in[4];
    const float* b_rel  = (const float*)d_in[5];
    const float* w_root = (const float*)d_in[6];
    const float* n0g    = (const float*)d_in[7];
    const float* n0b    = (const float*)d_in[8];
    const float* lin_w  = (const float*)d_in[9];
    const float* lin_b  = (const float*)d_in[10];
    const float* bnh_g  = (const float*)d_in[11];
    const float* bnh_b  = (const float*)d_in[12];
    const float* bno_g  = (const float*)d_in[13];
    const float* bno_b  = (const float*)d_in[14];
    const float* w1     = (const float*)d_in[15];
    const float* b1     = (const float*)d_in[16];
    const float* w2     = (const float*)d_in[17];
    const float* b2     = (const float*)d_in[18];
    const float* w3     = (const float*)d_in[19];
    const float* b3     = (const float*)d_in[20];
    float* out = (float*)d_out;
    const int* row = ei;
    const int* col = ei + NE;

    float *p_neigh, *p_X, *p_H1, *p_H2, *p_stX, *p_stH, *p_scX, *p_shX;
    float *p_Hbn, *p_h1, *p_h2, *p_xr, *p_wrelt, *p_wroott, *p_Hm;
    int *p_offc, *p_offr, *p_srcc, *p_srcr;
    cudaGetSymbolAddress((void**)&p_neigh, d_neigh);
    cudaGetSymbolAddress((void**)&p_X, d_X);
    cudaGetSymbolAddress((void**)&p_H1, d_H1);
    cudaGetSymbolAddress((void**)&p_H2, d_H2);
    cudaGetSymbolAddress((void**)&p_Hm, d_Hm);
    cudaGetSymbolAddress((void**)&p_stX, d_stX);
    cudaGetSymbolAddress((void**)&p_stH, d_stH);
    cudaGetSymbolAddress((void**)&p_scX, d_scX);
    cudaGetSymbolAddress((void**)&p_shX, d_shX);
    cudaGetSymbolAddress((void**)&p_Hbn, d_Hbn);
    cudaGetSymbolAddress((void**)&p_h1, d_h1);
    cudaGetSymbolAddress((void**)&p_h2, d_h2);
    cudaGetSymbolAddress((void**)&p_xr, d_xr);
    cudaGetSymbolAddress((void**)&p_wrelt, d_wrelt);
    cudaGetSymbolAddress((void**)&p_wroott, d_wroott);
    cudaGetSymbolAddress((void**)&p_offc, d_offc);
    cudaGetSymbolAddress((void**)&p_offr, d_offr);
    cudaGetSymbolAddress((void**)&p_srcc, d_srcc);
    cudaGetSymbolAddress((void**)&p_srcr, d_srcr);

    cudaFuncSetAttribute(gemm_x_k, cudaFuncAttributeMaxDynamicSharedMemorySize, GSMEM);
    cudaFuncSetAttribute(gemm_hm_k, cudaFuncAttributeMaxDynamicSharedMemorySize, GSMEM);

    const int ROWBLK = (NN + 127) / 128;   // 391
    const int NODEBLK = (NN + 7) / 8;      // 6250

    // ---- CSR build + operand rounding ----
    init_k<<<(NN + 255) / 256, 256>>>();
    hist_k<<<(NE + 255) / 256, 256>>>(row, col);
    scan_k<<<2, SCAN_T>>>();
    fill_k<<<(NE + 255) / 256, 256>>>(row, col);
    round_copy_k<<<(NN * CDIM + 255) / 256, 256>>>(x, p_xr, NN * CDIM);
    round_copy_k<<<(CDIM * CDIM + 255) / 256, 256>>>(w_rel, p_wrelt, CDIM * CDIM);
    round_copy_k<<<(CDIM * CDIM + 255) / 256, 256>>>(w_root, p_wroott, CDIM * CDIM);
    // neigh[n] = sum (dst=col) of x[src]  (stored tf32-rounded)
    spmm_csr_k<<<NODEBLK, 256>>>(x, p_neigh, p_offc, p_srcc, nullptr, nullptr);
    // X (fp32) + Xr (tf32) = neigh @ w_rel^T + x @ w_root^T + b_rel
    gemm_x_k<<<ROWBLK, 256, GSMEM>>>(b_rel);
    stats2_k<<<400, 256>>>(p_X, 128, p_stX, 125);
    finalize_bnX_k<<<1, 128>>>(n0g, n0b);
    lin_transform_k<<<M3, 128>>>(lin_w, lin_b);
    // H1 = A·BN(X) (affine fused, rounded); H2 = A·H1 (rounded)
    spmm_csr_k<<<NODEBLK, 256>>>(p_X, p_H1, p_offr, p_srcr, p_scX, p_shX);
    spmm_csr_k<<<NODEBLK, 256>>>(p_H1, p_H2, p_offr, p_srcr, nullptr, nullptr);
    // masked block-lower-triangular lin GEMM (BN folded into weights)
    gemm_hm_k<<<dim3(ROWBLK, 3), 256, GSMEM>>>();
    stats2_k<<<400, 384>>>(p_Hm, 384, p_stH, 125);
    pool_k<<<NG, 384>>>(batch, bnh_g, bnh_b);
    bn_graphs_k<<<CAT / 128, 128>>>(bno_g, bno_b);
    mlp_k<<<dim3(768 / 128, NG / 8), 128, 8 * 1152 * sizeof(float)>>>(
        p_Hbn, 1152, w1, b1, p_h1, 768, 1);
    mlp_k<<<dim3(384 / 128, NG / 8), 128, 8 * 768 * sizeof(float)>>>(
        p_h1, 768, w2, b2, p_h2, 384, 1);
    final_k<<<1, 128>>>(w3, b3, out);
}

// round 12
// speedup vs baseline: 1.1585x; 1.0222x over previous
#include <cuda_runtime.h>
#include <math.h>
#include <stdint.h>

#define NN 50000
#define NE 600000
#define NG 128
#define CDIM 128
#define M3 384
#define CAT 1152
#define EPSB 1e-5f
#define SCAN_T 1024
#define AST 36                       // smem row stride (words)
#define GSMEM (4 * 128 * AST * 4)    // 2 stages x (A+W) x 128x36 words

// ---------------- static scratch (no allocations allowed) ----------------
__device__ float d_neigh[(size_t)NN * CDIM];
__device__ float d_X[(size_t)NN * CDIM];
__device__ float d_Xr[(size_t)NN * CDIM];
__device__ float d_xr[(size_t)NN * CDIM];
__device__ float d_H1[(size_t)NN * CDIM];
__device__ float d_H2[(size_t)NN * CDIM];
__device__ float d_Hm[(size_t)NN * M3];
__device__ float d_wrelt[CDIM * CDIM];
__device__ float d_wroott[CDIM * CDIM];
__device__ float d_linwt[M3 * M3];
__device__ float d_linbt[M3];
__device__ float d_stX[2 * CDIM];
__device__ float d_stH[2 * M3];
__device__ float d_scX[CDIM];
__device__ float d_shX[CDIM];
__device__ float d_Hcat[NG * CAT];
__device__ float d_Hbn[NG * CAT];
__device__ float d_h1[NG * 768];
__device__ float d_h2[NG * 384];
// CSR scratch
__device__ int d_degc[NN], d_degr[NN];
__device__ int d_offc[NN + 1], d_offr[NN + 1];
__device__ int d_curc[NN], d_curr[NN];
__device__ int d_srcc[NE];
__device__ int d_srcr[NE];

// ---------------- tf32 helpers ----------------
__device__ __forceinline__ unsigned f2tf32(float v) {
    unsigned r;
    asm("cvt.rna.tf32.f32 %0, %1;" : "=r"(r) : "f"(v));
    return r;
}
__device__ __forceinline__ float rnd_tf32(float v) { return __uint_as_float(f2tf32(v)); }
__device__ __forceinline__ void mma_tf32(float* c, const unsigned* a, const unsigned* b) {
    asm volatile(
        "mma.sync.aligned.m16n8k8.row.col.f32.tf32.tf32.f32 "
        "{%0,%1,%2,%3}, {%4,%5,%6,%7}, {%8,%9}, {%0,%1,%2,%3};"
        : "+f"(c[0]), "+f"(c[1]), "+f"(c[2]), "+f"(c[3])
        : "r"(a[0]), "r"(a[1]), "r"(a[2]), "r"(a[3]), "r"(b[0]), "r"(b[1]));
}
// ---------------- cp.async helpers ----------------
__device__ __forceinline__ void cpa16(uint32_t saddr, const void* g, int bytes) {
    asm volatile("cp.async.cg.shared.global [%0], [%1], 16, %2;"
                 :: "r"(saddr), "l"(g), "r"(bytes));
}
__device__ __forceinline__ void cpa_commit() { asm volatile("cp.async.commit_group;"); }
__device__ __forceinline__ void cpa_wait1() { asm volatile("cp.async.wait_group 1;"); }
__device__ __forceinline__ void cpa_wait0() { asm volatile("cp.async.wait_group 0;"); }

// ---------------- init: zero degrees + stats accumulators ----------------
__global__ void init_k() {
    int i = blockIdx.x * blockDim.x + threadIdx.x;
    if (i < NN) { d_degc[i] = 0; d_degr[i] = 0; }
    if (i < 2 * CDIM) d_stX[i] = 0.f;
    if (i < 2 * M3) d_stH[i] = 0.f;
}

// ---------------- degree histogram ----------------
__global__ void hist_k(const int* __restrict__ row, const int* __restrict__ col) {
    int e = blockIdx.x * blockDim.x + threadIdx.x;
    if (e >= NE) return;
    atomicAdd(&d_degc[__ldg(col + e)], 1);
    atomicAdd(&d_degr[__ldg(row + e)], 1);
}

// ---------------- exclusive scan (single block per array) ----------------
__global__ void scan_k() {
    __shared__ int sm[SCAN_T];
    const int* deg = (blockIdx.x == 0) ? d_degc : d_degr;
    int* off = (blockIdx.x == 0) ? d_offc : d_offr;
    int* cur = (blockIdx.x == 0) ? d_curc : d_curr;
    int t = threadIdx.x;
    const int CH = (NN + SCAN_T - 1) / SCAN_T;
    int b = t * CH, e = min(b + CH, NN);
    int s = 0;
    for (int i = b; i < e; i++) s += deg[i];
    sm[t] = s;
    __syncthreads();
    for (int d = 1; d < SCAN_T; d <<= 1) {
        int u = (t >= d) ? sm[t - d] : 0;
        __syncthreads();
        sm[t] += u;
        __syncthreads();
    }
    int p = (t == 0) ? 0 : sm[t - 1];
    for (int i = b; i < e; i++) {
        off[i] = p;
        cur[i] = p;
        p += deg[i];
    }
    if (t == SCAN_T - 1) off[NN] = sm[SCAN_T - 1];
}

// ---------------- fill CSR edge lists ----------------
__global__ void fill_k(const int* __restrict__ row, const int* __restrict__ col) {
    int e = blockIdx.x * blockDim.x + threadIdx.x;
    if (e >= NE) return;
    int r = __ldg(row + e), c = __ldg(col + e);
    int pc = atomicAdd(&d_curc[c], 1);
    d_srcc[pc] = r;
    int pr = atomicAdd(&d_curr[r], 1);
    d_srcr[pr] = c;
}

// ---------------- round-copy (tf32 quantize) ----------------
__global__ void round_copy_k(const float* __restrict__ src, float* __restrict__ dst, int n) {
    int i = blockIdx.x * blockDim.x + threadIdx.x;
    if (i < n) dst[i] = rnd_tf32(__ldg(src + i));
}

// ---------------- CSR gather-accumulate (MLP-4 unrolled); stores tf32-rounded ----------------
__global__ void spmm_csr_k(const float* __restrict__ src, float* __restrict__ dst,
                           const int* __restrict__ off, const int* __restrict__ idx,
                           const float* __restrict__ sc, const float* __restrict__ sh) {
    int node = blockIdx.x * 8 + (threadIdx.x >> 5);
    if (node >= NN) return;
    int q = threadIdx.x & 31;
    int beg = __ldg(off + node), end = __ldg(off + node + 1);
    float4 acc = make_float4(0.f, 0.f, 0.f, 0.f);
    int e = beg;
    for (; e + 3 < end; e += 4) {
        int s0 = __ldg(idx + e), s1 = __ldg(idx + e + 1);
        int s2 = __ldg(idx + e + 2), s3 = __ldg(idx + e + 3);
        float4 v0 = __ldg((const float4*)src + (size_t)s0 * 32 + q);
        float4 v1 = __ldg((const float4*)src + (size_t)s1 * 32 + q);
        float4 v2 = __ldg((const float4*)src + (size_t)s2 * 32 + q);
        float4 v3 = __ldg((const float4*)src + (size_t)s3 * 32 + q);
        acc.x += (v0.x + v1.x) + (v2.x + v3.x);
        acc.y += (v0.y + v1.y) + (v2.y + v3.y);
        acc.z += (v0.z + v1.z) + (v2.z + v3.z);
        acc.w += (v0.w + v1.w) + (v2.w + v3.w);
    }
    for (; e < end; ++e) {
        int s0 = __ldg(idx + e);
        float4 v0 = __ldg((const float4*)src + (size_t)s0 * 32 + q);
        acc.x += v0.x; acc.y += v0.y; acc.z += v0.z; acc.w += v0.w;
    }
    if (sc) {
        float d = (float)(end - beg);
        float4 s4 = __ldg((const float4*)sc + q);
        float4 h4 = __ldg((const float4*)sh + q);
        acc.x = fmaf(acc.x, s4.x, h4.x * d);
        acc.y = fmaf(acc.y, s4.y, h4.y * d);
        acc.z = fmaf(acc.z, s4.z, h4.z * d);
        acc.w = fmaf(acc.w, s4.w, h4.w * d);
    }
    acc.x = rnd_tf32(acc.x); acc.y = rnd_tf32(acc.y);
    acc.z = rnd_tf32(acc.z); acc.w = rnd_tf32(acc.w);
    ((float4*)dst)[(size_t)node * 32 + q] = acc;
}

// ---------------- stage issue helper for async GEMM ----------------
__device__ __forceinline__ void gemm_issue_stage(
    const float* const* Ap, const float* const* Wp, int st, int ldw,
    int r0, int rrb, int kq, uint32_t sbase, int BUF) {
    const float* A = Ap[st >> 2];
    const float* W = Wp[st >> 2];
    int kb = (st & 3) * 32;
    uint32_t abase = sbase + (uint32_t)((st & 1) * BUF) * 4;
    uint32_t wbase = abase + 128 * AST * 4;
#pragma unroll
    for (int it = 0; it < 4; ++it) {
        int rr = rrb + it * 32;
        int r = r0 + rr;
        int ok = (r < NN);
        const float* ga = A + (size_t)(ok ? r : 0) * CDIM + kb + kq;
        cpa16(abase + (uint32_t)(rr * AST + kq) * 4, ga, ok ? 16 : 0);
        cpa16(wbase + (uint32_t)(rr * AST + kq) * 4, W + (size_t)rr * ldw + kb + kq, 16);
    }
    cpa_commit();
}

// ================= tf32 GEMM core, cp.async double-buffered =================
// All A/W operands are pre-rounded tf32 bits; MMA consumes raw smem words.
// smem layout (words): [A0 | W0 | A1 | W1], each 128*AST.
__device__ __forceinline__ void gemm_core_async(
    const float* const* Ap, const float* const* Wp, int nIn, int ldw,
    const float* __restrict__ bias, float* __restrict__ Cp, int ldc,
    int r0, int cbase, float* __restrict__ C2p, unsigned* smemu) {
    const int tx = threadIdx.x;
    const int lane = tx & 31;
    const int warp = tx >> 5;
    const int wr = (warp & 3) * 32;
    const int wc = (warp >> 2) * 64;
    const int g = lane >> 2;
    const int t4 = lane & 3;
    const int rrb = tx >> 3;        // 0..31
    const int kq = (tx & 7) * 4;    // 0..28
    const uint32_t sbase = (uint32_t)__cvta_generic_to_shared(smemu);
    const int BUF = 2 * 128 * AST;  // words per stage (A+W)

    float acc[2][8][4];
#pragma unroll
    for (int mi = 0; mi < 2; mi++)
#pragma unroll
        for (int ni = 0; ni < 8; ni++)
#pragma unroll
            for (int j = 0; j < 4; j++) acc[mi][ni][j] = 0.f;

    const int nSteps = nIn * 4;

    gemm_issue_stage(Ap, Wp, 0, ldw, r0, rrb, kq, sbase, BUF);
    for (int st = 0; st < nSteps; ++st) {
        if (st + 1 < nSteps) {
            gemm_issue_stage(Ap, Wp, st + 1, ldw, r0, rrb, kq, sbase, BUF);
            cpa_wait1();
        } else {
            cpa_wait0();
        }
        __syncthreads();
        const unsigned* Ab = smemu + (st & 1) * BUF;
        const unsigned* Wb = Ab + 128 * AST;
#pragma unroll
        for (int kk = 0; kk < 32; kk += 8) {
            unsigned a[2][4], b[8][2];
#pragma unroll
            for (int mi = 0; mi < 2; mi++) {
                int r = wr + mi * 16;
                a[mi][0] = Ab[(r + g) * AST + kk + t4];
                a[mi][1] = Ab[(r + g + 8) * AST + kk + t4];
                a[mi][2] = Ab[(r + g) * AST + kk + t4 + 4];
                a[mi][3] = Ab[(r + g + 8) * AST + kk + t4 + 4];
            }
#pragma unroll
            for (int ni = 0; ni < 8; ni++) {
                int n = wc + ni * 8 + g;
                b[ni][0] = Wb[n * AST + kk + t4];
                b[ni][1] = Wb[n * AST + kk + t4 + 4];
            }
#pragma unroll
            for (int mi = 0; mi < 2; mi++)
#pragma unroll
                for (int ni = 0; ni < 8; ni++)
                    mma_tf32(acc[mi][ni], a[mi], b[ni]);
        }
        __syncthreads();
    }

    // epilogue: bias, write (optionally also tf32-rounded secondary)
#pragma unroll
    for (int mi = 0; mi < 2; mi++) {
        int r1 = r0 + wr + mi * 16 + g;
        int r2 = r1 + 8;
#pragma unroll
        for (int ni = 0; ni < 8; ni++) {
            int cc = wc + ni * 8 + 2 * t4;
            float b0 = bias[cc], b1 = bias[cc + 1];
            if (r1 < NN) {
                float v0 = acc[mi][ni][0] + b0, v1 = acc[mi][ni][1] + b1;
                Cp[(size_t)r1 * ldc + cbase + cc] = v0;
                Cp[(size_t)r1 * ldc + cbase + cc + 1] = v1;
                if (C2p) {
                    C2p[(size_t)r1 * ldc + cbase + cc] = rnd_tf32(v0);
                    C2p[(size_t)r1 * ldc + cbase + cc + 1] = rnd_tf32(v1);
                }
            }
            if (r2 < NN) {
                float v2 = acc[mi][ni][2] + b0, v3 = acc[mi][ni][3] + b1;
                Cp[(size_t)r2 * ldc + cbase + cc] = v2;
                Cp[(size_t)r2 * ldc + cbase + cc + 1] = v3;
                if (C2p) {
                    C2p[(size_t)r2 * ldc + cbase + cc] = rnd_tf32(v2);
                    C2p[(size_t)r2 * ldc + cbase + cc + 1] = rnd_tf32(v3);
                }
            }
        }
    }
}

// X = neigh @ w_rel^T + xr @ w_root^T + b_rel ; also writes Xr (tf32-rounded)
__global__ void __launch_bounds__(256, 2) gemm_x_k(const float* __restrict__ bias) {
    extern __shared__ unsigned smemu[];
    const float* Ap[3] = {d_neigh, d_xr, nullptr};
    const float* Wp[3] = {d_wrelt, d_wroott, nullptr};
    gemm_core_async(Ap, Wp, 2, 128, bias, d_X, 128, blockIdx.x * 128, 0, d_Xr, smemu);
}

// Hm strips with BN(X) folded into transformed weights/bias
__global__ void __launch_bounds__(256, 2) gemm_hm_k() {
    extern __shared__ unsigned smemu[];
    int j = blockIdx.y;
    const float* Ap[3] = {d_Xr, d_H1, d_H2};
    const float* Wp[3];
    for (int i = 0; i < 3; i++)
        Wp[i] = d_linwt + (size_t)(j * 128) * M3 + i * 128;
    gemm_core_async(Ap, Wp, j + 1, M3, d_linbt + j * 128, d_Hm, M3,
                    blockIdx.x * 128, j * 128, nullptr, smemu);
}

// ---------------- per-column sum/sumsq over NN rows ----------------
__global__ void stats2_k(const float* __restrict__ A, int ncol, float* __restrict__ st,
                         int rows_per_blk) {
    __shared__ float sm[384 * 8];
    int n4 = ncol >> 2;
    int c4 = threadIdx.x % n4;
    int rl = threadIdx.x / n4;
    int rstep = blockDim.x / n4;
    int r0 = blockIdx.x * rows_per_blk;
    int rend = min(r0 + rows_per_blk, NN);
    float4 s = make_float4(0, 0, 0, 0), q = make_float4(0, 0, 0, 0);
    for (int r = r0 + rl; r < rend; r += rstep) {
        float4 v = __ldg((const float4*)(A + (size_t)r * ncol) + c4);
        s.x += v.x; s.y += v.y; s.z += v.z; s.w += v.w;
        q.x += v.x * v.x; q.y += v.y * v.y; q.z += v.z * v.z; q.w += v.w * v.w;
    }
    float* my = sm + threadIdx.x * 8;
    my[0] = s.x; my[1] = s.y; my[2] = s.z; my[3] = s.w;
    my[4] = q.x; my[5] = q.y; my[6] = q.z; my[7] = q.w;
    __syncthreads();
    if (threadIdx.x < (unsigned)n4) {
        float acc[8];
#pragma unroll
        for (int k = 0; k < 8; k++) acc[k] = 0.f;
        for (int j = 0; j < rstep; j++) {
            float* p = sm + (c4 + j * n4) * 8;
#pragma unroll
            for (int k = 0; k < 8; k++) acc[k] += p[k];
        }
#pragma unroll
        for (int k = 0; k < 4; k++) {
            atomicAdd(st + c4 * 4 + k, acc[k]);
            atomicAdd(st + ncol + c4 * 4 + k, acc[4 + k]);
        }
    }
}

// ---------------- finalize BN(X): stats -> per-channel scale/shift ----------------
__global__ void finalize_bnX_k(const float* __restrict__ gw, const float* __restrict__ gb) {
    int c = threadIdx.x;  // 128
    float mean = d_stX[c] * (1.f / NN);
    float var = d_stX[CDIM + c] * (1.f / NN) - mean * mean;
    float sc = gw[c] * rsqrtf(var + EPSB);
    d_scX[c] = sc;
    d_shX[c] = gb[c] - mean * sc;
}

// ---------------- fold BN(X) into lin weights/bias; tf32-round all of lin_w ----------------
__global__ void lin_transform_k(const float* __restrict__ lin_w, const float* __restrict__ lin_b) {
    __shared__ float red[128];
    int o = blockIdx.x;   // 0..383
    int t = threadIdx.x;  // 0..127
    const float* wrow = lin_w + (size_t)o * M3;
    float w0 = wrow[t];
    d_linwt[(size_t)o * M3 + t] = rnd_tf32(w0 * d_scX[t]);
    d_linwt[(size_t)o * M3 + 128 + t] = rnd_tf32(wrow[128 + t]);
    d_linwt[(size_t)o * M3 + 256 + t] = rnd_tf32(wrow[256 + t]);
    red[t] = d_shX[t] * w0;
    __syncthreads();
    for (int s2 = 64; s2 > 0; s2 >>= 1) {
        if (t < s2) red[t] += red[t + s2];
        __syncthreads();
    }
    if (t == 0) d_linbt[o] = lin_b[o] + red[0];
}

// ---------------- pooling (fuses bnh BatchNorm apply) ----------------
__global__ void pool_k(const int* __restrict__ batch,
                       const float* __restrict__ gw, const float* __restrict__ gb) {
    int g = blockIdx.x;
    int c = threadIdx.x;  // 384
    int lo = 0, hi = NN;
    while (lo < hi) { int mid = (lo + hi) >> 1; if (batch[mid] < g) lo = mid + 1; else hi = mid; }
    int start = lo;
    lo = start; hi = NN;
    while (lo < hi) { int mid = (lo + hi) >> 1; if (batch[mid] < g + 1) lo = mid + 1; else hi = mid; }
    int end = lo;

    float mean = d_stH[c] * (1.f / NN);
    float var = d_stH[M3 + c] * (1.f / NN) - mean * mean;
    float sc = gw[c] * rsqrtf(var + EPSB);
    float sh = gb[c] - mean * sc;

    float s = 0.f;
    float mx = -INFINITY;
    for (int r = start; r < end; ++r) {
        float v = fmaf(d_Hm[(size_t)r * M3 + c], sc, sh);
        s += v;
        mx = fmaxf(mx, v);
    }
    int cnt = end - start;
    d_Hcat[(size_t)g * CAT + c] = (cnt > 0) ? s / (float)cnt : 0.f;
    d_Hcat[(size_t)g * CAT + 384 + c] = s;
    d_Hcat[(size_t)g * CAT + 768 + c] = (cnt > 0) ? mx : 0.f;
}

// ---------------- BN over graphs ----------------
__global__ void bn_graphs_k(const float* __restrict__ gw, const float* __restrict__ gb) {
    int c = blockIdx.x * blockDim.x + threadIdx.x;
    if (c >= CAT) return;
    float s = 0.f, ss = 0.f;
    for (int r = 0; r < NG; r++) { float v = d_Hcat[r * CAT + c]; s += v; ss += v * v; }
    float mean = s * (1.f / NG);
    float var = ss * (1.f / NG) - mean * mean;
    float sc = gw[c] * rsqrtf(var + EPSB);
    float sh = gb[c] - mean * sc;
    for (int r = 0; r < NG; r++) d_Hbn[r * CAT + c] = fmaf(d_Hcat[r * CAT + c], sc, sh);
}

// ---------------- small dense layer ----------------
__global__ void mlp_k(const float* __restrict__ A, int Kd,
                      const float* __restrict__ W, const float* __restrict__ bias,
                      float* __restrict__ out, int Od, int do_relu) {
    extern __shared__ float sA[];
    int g0 = blockIdx.y * 8;
    for (int idx = threadIdx.x; idx < 8 * Kd; idx += blockDim.x)
        sA[idx] = A[(size_t)(g0 + idx / Kd) * Kd + (idx % Kd)];
    __syncthreads();
    int o = blockIdx.x * blockDim.x + threadIdx.x;
    float bb = bias[o];
    float acc[8];
#pragma unroll
    for (int j = 0; j < 8; j++) acc[j] = bb;
    const float* wr = W + (size_t)o * Kd;
    for (int k = 0; k < Kd; k++) {
        float w = wr[k];
#pragma unroll
        for (int j = 0; j < 8; j++) acc[j] = fmaf(w, sA[j * Kd + k], acc[j]);
    }
#pragma unroll
    for (int j = 0; j < 8; j++) {
        float v = acc[j];
        if (do_relu) v = fmaxf(v, 0.f);
        out[(size_t)(g0 + j) * Od + o] = v;
    }
}

// ---------------- final layer + log_softmax ----------------
__global__ void final_k(const float* __restrict__ w3, const float* __restrict__ b3,
                        float* __restrict__ out) {
    int g = threadIdx.x;
    if (g >= NG) return;
    float l0 = b3[0], l1 = b3[1];
    const float* h = d_h2 + (size_t)g * 384;
    for (int k = 0; k < 384; k++) {
        float v = h[k];
        l0 = fmaf(v, w3[k], l0);
        l1 = fmaf(v, w3[384 + k], l1);
    }
    float m = fmaxf(l0, l1);
    float lse = m + logf(expf(l0 - m) + expf(l1 - m));
    out[g * 2 + 0] = l0 - lse;
    out[g * 2 + 1] = l1 - lse;
}

extern "C" void kernel_launch(void* const* d_in, const int* in_sizes, int n_in,
                              void* d_out, int out_size) {
    const float* x      = (const float*)d_in[0];
    const int*   ei     = (const int*)d_in[1];
    const int*   batch  = (const int*)d_in[2];
    const float* w_rel  = (const float*)d_in[4];
    const float* b_rel  = (const float*)d_in[5];
    const float* w_root = (const float*)d_in[6];
    const float* n0g    = (const float*)d_in[7];
    const float* n0b    = (const float*)d_in[8];
    const float* lin_w  = (const float*)d_in[9];
    const float* lin_b  = (const float*)d_in[10];
    const float* bnh_g  = (const float*)d_in[11];
    const float* bnh_b  = (const float*)d_in[12];
    const float* bno_g  = (const float*)d_in[13];
    const float* bno_b  = (const float*)d_in[14];
    const float* w1     = (const float*)d_in[15];
    const float* b1     = (const float*)d_in[16];
    const float* w2     = (const float*)d_in[17];
    const float* b2     = (const float*)d_in[18];
    const float* w3     = (const float*)d_in[19];
    const float* b3     = (const float*)d_in[20];
    float* out = (float*)d_out;
    const int* row = ei;
    const int* col = ei + NE;

    float *p_neigh, *p_X, *p_H1, *p_H2, *p_stX, *p_stH, *p_scX, *p_shX;
    float *p_Hbn, *p_h1, *p_h2, *p_xr, *p_wrelt, *p_wroott, *p_Hm;
    int *p_offc, *p_offr, *p_srcc, *p_srcr;
    cudaGetSymbolAddress((void**)&p_neigh, d_neigh);
    cudaGetSymbolAddress((void**)&p_X, d_X);
    cudaGetSymbolAddress((void**)&p_H1, d_H1);
    cudaGetSymbolAddress((void**)&p_H2, d_H2);
    cudaGetSymbolAddress((void**)&p_Hm, d_Hm);
    cudaGetSymbolAddress((void**)&p_stX, d_stX);
    cudaGetSymbolAddress((void**)&p_stH, d_stH);
    cudaGetSymbolAddress((void**)&p_scX, d_scX);
    cudaGetSymbolAddress((void**)&p_shX, d_shX);
    cudaGetSymbolAddress((void**)&p_Hbn, d_Hbn);
    cudaGetSymbolAddress((void**)&p_h1, d_h1);
    cudaGetSymbolAddress((void**)&p_h2, d_h2);
    cudaGetSymbolAddress((void**)&p_xr, d_xr);
    cudaGetSymbolAddress((void**)&p_wrelt, d_wrelt);
    cudaGetSymbolAddress((void**)&p_wroott, d_wroott);
    cudaGetSymbolAddress((void**)&p_offc, d_offc);
    cudaGetSymbolAddress((void**)&p_offr, d_offr);
    cudaGetSymbolAddress((void**)&p_srcc, d_srcc);
    cudaGetSymbolAddress((void**)&p_srcr, d_srcr);

    cudaFuncSetAttribute(gemm_x_k, cudaFuncAttributeMaxDynamicSharedMemorySize, GSMEM);
    cudaFuncSetAttribute(gemm_hm_k, cudaFuncAttributeMaxDynamicSharedMemorySize, GSMEM);

    const int ROWBLK = (NN + 127) / 128;   // 391
    const int NODEBLK = (NN + 7) / 8;      // 6250

    // ---- CSR build + operand rounding ----
    init_k<<<(NN + 255) / 256, 256>>>();
    hist_k<<<(NE + 255) / 256, 256>>>(row, col);
    scan_k<<<2, SCAN_T>>>();
    fill_k<<<(NE + 255) / 256, 256>>>(row, col);
    round_copy_k<<<(NN * CDIM + 255) / 256, 256>>>(x, p_xr, NN * CDIM);
    round_copy_k<<<(CDIM * CDIM + 255) / 256, 256>>>(w_rel, p_wrelt, CDIM * CDIM);
    round_copy_k<<<(CDIM * CDIM + 255) / 256, 256>>>(w_root, p_wroott, CDIM * CDIM);
    // neigh[n] = sum (dst=col) of x[src]  (stored tf32-rounded)
    spmm_csr_k<<<NODEBLK, 256>>>(x, p_neigh, p_offc, p_srcc, nullptr, nullptr);
    // X (fp32) + Xr (tf32) = neigh @ w_rel^T + x @ w_root^T + b_rel
    gemm_x_k<<<ROWBLK, 256, GSMEM>>>(b_rel);
    stats2_k<<<400, 256>>>(p_X, 128, p_stX, 125);
    finalize_bnX_k<<<1, 128>>>(n0g, n0b);
    lin_transform_k<<<M3, 128>>>(lin_w, lin_b);
    // H1 = A·BN(X) (affine fused, rounded); H2 = A·H1 (rounded)
    spmm_csr_k<<<NODEBLK, 256>>>(p_X, p_H1, p_offr, p_srcr, p_scX, p_shX);
    spmm_csr_k<<<NODEBLK, 256>>>(p_H1, p_H2, p_offr, p_srcr, nullptr, nullptr);
    // masked block-lower-triangular lin GEMM (BN folded into weights)
    gemm_hm_k<<<dim3(ROWBLK, 3), 256, GSMEM>>>();
    stats2_k<<<400, 384>>>(p_Hm, 384, p_stH, 125);
    pool_k<<<NG, 384>>>(batch, bnh_g, bnh_b);
    bn_graphs_k<<<CAT / 128, 128>>>(bno_g, bno_b);
    mlp_k<<<dim3(768 / 128, NG / 8), 128, 8 * 1152 * sizeof(float)>>>(
        p_Hbn, 1152, w1, b1, p_h1, 768, 1);
    mlp_k<<<dim3(384 / 128, NG / 8), 128, 8 * 768 * sizeof(float)>>>(
        p_h1, 768, w2, b2, p_h2, 384, 1);
    final_k<<<1, 128>>>(w3, b3, out);
}

// round 13
// speedup vs baseline: 1.1997x; 1.0355x over previous
#include <cuda_runtime.h>
#include <math.h>
#include <stdint.h>

#define NN 50000
#define NE 600000
#define NG 128
#define CDIM 128
#define M3 384
#define CAT 1152
#define EPSB 1e-5f
#define SCAN_T 1024
#define AST 36                       // smem row stride (words)
#define GSMEM (4 * 128 * AST * 4)    // 2 stages x (A+W) x 128x36 words

// ---------------- static scratch (no allocations allowed) ----------------
__device__ float d_neigh[(size_t)NN * CDIM];
__device__ float d_Xr[(size_t)NN * CDIM];
__device__ float d_xr[(size_t)NN * CDIM];
__device__ float d_H1[(size_t)NN * CDIM];
__device__ float d_H2[(size_t)NN * CDIM];
__device__ float d_Hm[(size_t)NN * M3];
__device__ float d_wrelt[CDIM * CDIM];
__device__ float d_wroott[CDIM * CDIM];
__device__ float d_linwt[M3 * M3];
__device__ float d_linbt[M3];
__device__ float d_stX[2 * CDIM];
__device__ float d_scX[CDIM];
__device__ float d_shX[CDIM];
__device__ float d_scH[M3];
__device__ float d_shH[M3];
__device__ float d_gsum[NG * M3];
__device__ float d_gsq[NG * M3];
__device__ float d_gmax[NG * M3];
__device__ float d_gmin[NG * M3];
__device__ int   d_gcnt[NG];
__device__ float d_Hcat[NG * CAT];
__device__ float d_Hbn[NG * CAT];
__device__ float d_h1[NG * 768];
__device__ float d_h2[NG * 384];
// CSR scratch
__device__ int d_degc[NN], d_degr[NN];
__device__ int d_offc[NN + 1], d_offr[NN + 1];
__device__ int d_curc[NN], d_curr[NN];
__device__ int d_srcc[NE];
__device__ int d_srcr[NE];

// ---------------- tf32 helpers ----------------
__device__ __forceinline__ unsigned f2tf32(float v) {
    unsigned r;
    asm("cvt.rna.tf32.f32 %0, %1;" : "=r"(r) : "f"(v));
    return r;
}
__device__ __forceinline__ float rnd_tf32(float v) { return __uint_as_float(f2tf32(v)); }
__device__ __forceinline__ void mma_tf32(float* c, const unsigned* a, const unsigned* b) {
    asm volatile(
        "mma.sync.aligned.m16n8k8.row.col.f32.tf32.tf32.f32 "
        "{%0,%1,%2,%3}, {%4,%5,%6,%7}, {%8,%9}, {%0,%1,%2,%3};"
        : "+f"(c[0]), "+f"(c[1]), "+f"(c[2]), "+f"(c[3])
        : "r"(a[0]), "r"(a[1]), "r"(a[2]), "r"(a[3]), "r"(b[0]), "r"(b[1]));
}
// ---------------- cp.async helpers ----------------
__device__ __forceinline__ void cpa16(uint32_t saddr, const void* g, int bytes) {
    asm volatile("cp.async.cg.shared.global [%0], [%1], 16, %2;"
                 :: "r"(saddr), "l"(g), "r"(bytes));
}
__device__ __forceinline__ void cpa_commit() { asm volatile("cp.async.commit_group;"); }
__device__ __forceinline__ void cpa_wait1() { asm volatile("cp.async.wait_group 1;"); }
__device__ __forceinline__ void cpa_wait0() { asm volatile("cp.async.wait_group 0;"); }

// ---------------- init: zero degrees + stats accumulators ----------------
__global__ void init_k() {
    int i = blockIdx.x * blockDim.x + threadIdx.x;
    if (i < NN) { d_degc[i] = 0; d_degr[i] = 0; }
    if (i < 2 * CDIM) d_stX[i] = 0.f;
}

// ---------------- degree histogram ----------------
__global__ void hist_k(const int* __restrict__ row, const int* __restrict__ col) {
    int e = blockIdx.x * blockDim.x + threadIdx.x;
    if (e >= NE) return;
    atomicAdd(&d_degc[__ldg(col + e)], 1);
    atomicAdd(&d_degr[__ldg(row + e)], 1);
}

// ---------------- exclusive scan (single block per array) ----------------
__global__ void scan_k() {
    __shared__ int sm[SCAN_T];
    const int* deg = (blockIdx.x == 0) ? d_degc : d_degr;
    int* off = (blockIdx.x == 0) ? d_offc : d_offr;
    int* cur = (blockIdx.x == 0) ? d_curc : d_curr;
    int t = threadIdx.x;
    const int CH = (NN + SCAN_T - 1) / SCAN_T;
    int b = t * CH, e = min(b + CH, NN);
    int s = 0;
    for (int i = b; i < e; i++) s += deg[i];
    sm[t] = s;
    __syncthreads();
    for (int d = 1; d < SCAN_T; d <<= 1) {
        int u = (t >= d) ? sm[t - d] : 0;
        __syncthreads();
        sm[t] += u;
        __syncthreads();
    }
    int p = (t == 0) ? 0 : sm[t - 1];
    for (int i = b; i < e; i++) {
        off[i] = p;
        cur[i] = p;
        p += deg[i];
    }
    if (t == SCAN_T - 1) off[NN] = sm[SCAN_T - 1];
}

// ---------------- fill CSR edge lists ----------------
__global__ void fill_k(const int* __restrict__ row, const int* __restrict__ col) {
    int e = blockIdx.x * blockDim.x + threadIdx.x;
    if (e >= NE) return;
    int r = __ldg(row + e), c = __ldg(col + e);
    int pc = atomicAdd(&d_curc[c], 1);
    d_srcc[pc] = r;
    int pr = atomicAdd(&d_curr[r], 1);
    d_srcr[pr] = c;
}

// ---------------- round-copy (tf32 quantize) ----------------
__global__ void round_copy_k(const float* __restrict__ src, float* __restrict__ dst, int n) {
    int i = blockIdx.x * blockDim.x + threadIdx.x;
    if (i < n) dst[i] = rnd_tf32(__ldg(src + i));
}

// ---------------- CSR gather-accumulate (MLP-4 unrolled); stores tf32-rounded ----------------
__global__ void spmm_csr_k(const float* __restrict__ src, float* __restrict__ dst,
                           const int* __restrict__ off, const int* __restrict__ idx,
                           const float* __restrict__ sc, const float* __restrict__ sh) {
    int node = blockIdx.x * 8 + (threadIdx.x >> 5);
    if (node >= NN) return;
    int q = threadIdx.x & 31;
    int beg = __ldg(off + node), end = __ldg(off + node + 1);
    float4 acc = make_float4(0.f, 0.f, 0.f, 0.f);
    int e = beg;
    for (; e + 3 < end; e += 4) {
        int s0 = __ldg(idx + e), s1 = __ldg(idx + e + 1);
        int s2 = __ldg(idx + e + 2), s3 = __ldg(idx + e + 3);
        float4 v0 = __ldg((const float4*)src + (size_t)s0 * 32 + q);
        float4 v1 = __ldg((const float4*)src + (size_t)s1 * 32 + q);
        float4 v2 = __ldg((const float4*)src + (size_t)s2 * 32 + q);
        float4 v3 = __ldg((const float4*)src + (size_t)s3 * 32 + q);
        acc.x += (v0.x + v1.x) + (v2.x + v3.x);
        acc.y += (v0.y + v1.y) + (v2.y + v3.y);
        acc.z += (v0.z + v1.z) + (v2.z + v3.z);
        acc.w += (v0.w + v1.w) + (v2.w + v3.w);
    }
    for (; e < end; ++e) {
        int s0 = __ldg(idx + e);
        float4 v0 = __ldg((const float4*)src + (size_t)s0 * 32 + q);
        acc.x += v0.x; acc.y += v0.y; acc.z += v0.z; acc.w += v0.w;
    }
    if (sc) {
        float d = (float)(end - beg);
        float4 s4 = __ldg((const float4*)sc + q);
        float4 h4 = __ldg((const float4*)sh + q);
        acc.x = fmaf(acc.x, s4.x, h4.x * d);
        acc.y = fmaf(acc.y, s4.y, h4.y * d);
        acc.z = fmaf(acc.z, s4.z, h4.z * d);
        acc.w = fmaf(acc.w, s4.w, h4.w * d);
    }
    acc.x = rnd_tf32(acc.x); acc.y = rnd_tf32(acc.y);
    acc.z = rnd_tf32(acc.z); acc.w = rnd_tf32(acc.w);
    ((float4*)dst)[(size_t)node * 32 + q] = acc;
}

// ---------------- stage issue helper for async GEMM ----------------
__device__ __forceinline__ void gemm_issue_stage(
    const float* const* Ap, const float* const* Wp, int st, int ldw,
    int r0, int rrb, int kq, uint32_t sbase, int BUF) {
    const float* A = Ap[st >> 2];
    const float* W = Wp[st >> 2];
    int kb = (st & 3) * 32;
    uint32_t abase = sbase + (uint32_t)((st & 1) * BUF) * 4;
    uint32_t wbase = abase + 128 * AST * 4;
#pragma unroll
    for (int it = 0; it < 4; ++it) {
        int rr = rrb + it * 32;
        int r = r0 + rr;
        int ok = (r < NN);
        const float* ga = A + (size_t)(ok ? r : 0) * CDIM + kb + kq;
        cpa16(abase + (uint32_t)(rr * AST + kq) * 4, ga, ok ? 16 : 0);
        cpa16(wbase + (uint32_t)(rr * AST + kq) * 4, W + (size_t)rr * ldw + kb + kq, 16);
    }
    cpa_commit();
}

// ================= tf32 GEMM core, cp.async double-buffered =================
__device__ __forceinline__ void gemm_core_async(
    const float* const* Ap, const float* const* Wp, int nIn, int ldw,
    const float* __restrict__ bias, float* __restrict__ Cp, int ldc,
    int r0, int cbase, int round_primary, unsigned* smemu) {
    const int tx = threadIdx.x;
    const int lane = tx & 31;
    const int warp = tx >> 5;
    const int wr = (warp & 3) * 32;
    const int wc = (warp >> 2) * 64;
    const int g = lane >> 2;
    const int t4 = lane & 3;
    const int rrb = tx >> 3;        // 0..31
    const int kq = (tx & 7) * 4;    // 0..28
    const uint32_t sbase = (uint32_t)__cvta_generic_to_shared(smemu);
    const int BUF = 2 * 128 * AST;  // words per stage (A+W)

    float acc[2][8][4];
#pragma unroll
    for (int mi = 0; mi < 2; mi++)
#pragma unroll
        for (int ni = 0; ni < 8; ni++)
#pragma unroll
            for (int j = 0; j < 4; j++) acc[mi][ni][j] = 0.f;

    const int nSteps = nIn * 4;

    gemm_issue_stage(Ap, Wp, 0, ldw, r0, rrb, kq, sbase, BUF);
    for (int st = 0; st < nSteps; ++st) {
        if (st + 1 < nSteps) {
            gemm_issue_stage(Ap, Wp, st + 1, ldw, r0, rrb, kq, sbase, BUF);
            cpa_wait1();
        } else {
            cpa_wait0();
        }
        __syncthreads();
        const unsigned* Ab = smemu + (st & 1) * BUF;
        const unsigned* Wb = Ab + 128 * AST;
#pragma unroll
        for (int kk = 0; kk < 32; kk += 8) {
            unsigned a[2][4], b[8][2];
#pragma unroll
            for (int mi = 0; mi < 2; mi++) {
                int r = wr + mi * 16;
                a[mi][0] = Ab[(r + g) * AST + kk + t4];
                a[mi][1] = Ab[(r + g + 8) * AST + kk + t4];
                a[mi][2] = Ab[(r + g) * AST + kk + t4 + 4];
                a[mi][3] = Ab[(r + g + 8) * AST + kk + t4 + 4];
            }
#pragma unroll
            for (int ni = 0; ni < 8; ni++) {
                int n = wc + ni * 8 + g;
                b[ni][0] = Wb[n * AST + kk + t4];
                b[ni][1] = Wb[n * AST + kk + t4 + 4];
            }
#pragma unroll
            for (int mi = 0; mi < 2; mi++)
#pragma unroll
                for (int ni = 0; ni < 8; ni++)
                    mma_tf32(acc[mi][ni], a[mi], b[ni]);
        }
        __syncthreads();
    }

    // epilogue: bias, optional tf32 rounding, write
#pragma unroll
    for (int mi = 0; mi < 2; mi++) {
        int r1 = r0 + wr + mi * 16 + g;
        int r2 = r1 + 8;
#pragma unroll
        for (int ni = 0; ni < 8; ni++) {
            int cc = wc + ni * 8 + 2 * t4;
            float b0 = bias[cc], b1 = bias[cc + 1];
            if (r1 < NN) {
                float v0 = acc[mi][ni][0] + b0, v1 = acc[mi][ni][1] + b1;
                if (round_primary) { v0 = rnd_tf32(v0); v1 = rnd_tf32(v1); }
                Cp[(size_t)r1 * ldc + cbase + cc] = v0;
                Cp[(size_t)r1 * ldc + cbase + cc + 1] = v1;
            }
            if (r2 < NN) {
                float v2 = acc[mi][ni][2] + b0, v3 = acc[mi][ni][3] + b1;
                if (round_primary) { v2 = rnd_tf32(v2); v3 = rnd_tf32(v3); }
                Cp[(size_t)r2 * ldc + cbase + cc] = v2;
                Cp[(size_t)r2 * ldc + cbase + cc + 1] = v3;
            }
        }
    }
}

// Xr = tf32( neigh @ w_rel^T + xr @ w_root^T + b_rel )
__global__ void __launch_bounds__(256, 2) gemm_x_k(const float* __restrict__ bias) {
    extern __shared__ unsigned smemu[];
    const float* Ap[3] = {d_neigh, d_xr, nullptr};
    const float* Wp[3] = {d_wrelt, d_wroott, nullptr};
    gemm_core_async(Ap, Wp, 2, 128, bias, d_Xr, 128, blockIdx.x * 128, 0, 1, smemu);
}

// Hm strips with BN(X) folded into transformed weights/bias
__global__ void __launch_bounds__(256, 2) gemm_hm_k() {
    extern __shared__ unsigned smemu[];
    int j = blockIdx.y;
    const float* Ap[3] = {d_Xr, d_H1, d_H2};
    const float* Wp[3];
    for (int i = 0; i < 3; i++)
        Wp[i] = d_linwt + (size_t)(j * 128) * M3 + i * 128;
    gemm_core_async(Ap, Wp, j + 1, M3, d_linbt + j * 128, d_Hm, M3,
                    blockIdx.x * 128, j * 128, 0, smemu);
}

// ---------------- per-column sum/sumsq over NN rows (X only) ----------------
__global__ void stats2_k(const float* __restrict__ A, int ncol, float* __restrict__ st,
                         int rows_per_blk) {
    __shared__ float sm[384 * 8];
    int n4 = ncol >> 2;
    int c4 = threadIdx.x % n4;
    int rl = threadIdx.x / n4;
    int rstep = blockDim.x / n4;
    int r0 = blockIdx.x * rows_per_blk;
    int rend = min(r0 + rows_per_blk, NN);
    float4 s = make_float4(0, 0, 0, 0), q = make_float4(0, 0, 0, 0);
    for (int r = r0 + rl; r < rend; r += rstep) {
        float4 v = __ldg((const float4*)(A + (size_t)r * ncol) + c4);
        s.x += v.x; s.y += v.y; s.z += v.z; s.w += v.w;
        q.x += v.x * v.x; q.y += v.y * v.y; q.z += v.z * v.z; q.w += v.w * v.w;
    }
    float* my = sm + threadIdx.x * 8;
    my[0] = s.x; my[1] = s.y; my[2] = s.z; my[3] = s.w;
    my[4] = q.x; my[5] = q.y; my[6] = q.z; my[7] = q.w;
    __syncthreads();
    if (threadIdx.x < (unsigned)n4) {
        float acc[8];
#pragma unroll
        for (int k = 0; k < 8; k++) acc[k] = 0.f;
        for (int j = 0; j < rstep; j++) {
            float* p = sm + (c4 + j * n4) * 8;
#pragma unroll
            for (int k = 0; k < 8; k++) acc[k] += p[k];
        }
#pragma unroll
        for (int k = 0; k < 4; k++) {
            atomicAdd(st + c4 * 4 + k, acc[k]);
            atomicAdd(st + ncol + c4 * 4 + k, acc[4 + k]);
        }
    }
}

// ---------------- finalize BN(X): stats -> per-channel scale/shift ----------------
__global__ void finalize_bnX_k(const float* __restrict__ gw, const float* __restrict__ gb) {
    int c = threadIdx.x;  // 128
    float mean = d_stX[c] * (1.f / NN);
    float var = d_stX[CDIM + c] * (1.f / NN) - mean * mean;
    float sc = gw[c] * rsqrtf(var + EPSB);
    d_scX[c] = sc;
    d_shX[c] = gb[c] - mean * sc;
}

// ---------------- fold BN(X) into lin weights/bias; tf32-round all of lin_w ----------------
__global__ void lin_transform_k(const float* __restrict__ lin_w, const float* __restrict__ lin_b) {
    __shared__ float red[128];
    int o = blockIdx.x;   // 0..383
    int t = threadIdx.x;  // 0..127
    const float* wrow = lin_w + (size_t)o * M3;
    float w0 = wrow[t];
    d_linwt[(size_t)o * M3 + t] = rnd_tf32(w0 * d_scX[t]);
    d_linwt[(size_t)o * M3 + 128 + t] = rnd_tf32(wrow[128 + t]);
    d_linwt[(size_t)o * M3 + 256 + t] = rnd_tf32(wrow[256 + t]);
    red[t] = d_shX[t] * w0;
    __syncthreads();
    for (int s2 = 64; s2 > 0; s2 >>= 1) {
        if (t < s2) red[t] += red[t + s2];
        __syncthreads();
    }
    if (t == 0) d_linbt[o] = lin_b[o] + red[0];
}

// ---------------- per-graph raw pooling over Hm: sum/sumsq/max/min ----------------
// One block per graph; 384 threads = 96 col-quads x 4 row-lanes; float4 loads.
__global__ void pool_raw_k(const int* __restrict__ batch) {
    __shared__ float sm[384 * 16];
    int gph = blockIdx.x;
    int tx = threadIdx.x;
    int c4 = tx % 96;
    int rl = tx / 96;
    int lo = 0, hi = NN;
    while (lo < hi) { int m = (lo + hi) >> 1; if (batch[m] < gph) lo = m + 1; else hi = m; }
    int start = lo;
    lo = start; hi = NN;
    while (lo < hi) { int m = (lo + hi) >> 1; if (batch[m] < gph + 1) lo = m + 1; else hi = m; }
    int end = lo;

    float4 s = make_float4(0, 0, 0, 0), q = make_float4(0, 0, 0, 0);
    float4 mx = make_float4(-INFINITY, -INFINITY, -INFINITY, -INFINITY);
    float4 mn = make_float4(INFINITY, INFINITY, INFINITY, INFINITY);
    for (int r = start + rl; r < end; r += 4) {
        float4 v = __ldg((const float4*)(d_Hm + (size_t)r * M3) + c4);
        s.x += v.x; s.y += v.y; s.z += v.z; s.w += v.w;
        q.x += v.x * v.x; q.y += v.y * v.y; q.z += v.z * v.z; q.w += v.w * v.w;
        mx.x = fmaxf(mx.x, v.x); mx.y = fmaxf(mx.y, v.y);
        mx.z = fmaxf(mx.z, v.z); mx.w = fmaxf(mx.w, v.w);
        mn.x = fminf(mn.x, v.x); mn.y = fminf(mn.y, v.y);
        mn.z = fminf(mn.z, v.z); mn.w = fminf(mn.w, v.w);
    }
    float* my = sm + tx * 16;
    my[0] = s.x; my[1] = s.y; my[2] = s.z; my[3] = s.w;
    my[4] = q.x; my[5] = q.y; my[6] = q.z; my[7] = q.w;
    my[8] = mx.x; my[9] = mx.y; my[10] = mx.z; my[11] = mx.w;
    my[12] = mn.x; my[13] = mn.y; my[14] = mn.z; my[15] = mn.w;
    __syncthreads();
    if (rl == 0) {  // tx < 96
        float a[16];
#pragma unroll
        for (int k = 0; k < 16; k++) a[k] = my[k];
        for (int j = 1; j < 4; j++) {
            float* p = sm + (tx + j * 96) * 16;
#pragma unroll
            for (int k = 0; k < 4; k++) {
                a[k] += p[k];
                a[4 + k] += p[4 + k];
                a[8 + k] = fmaxf(a[8 + k], p[8 + k]);
                a[12 + k] = fminf(a[12 + k], p[12 + k]);
            }
        }
#pragma unroll
        for (int k = 0; k < 4; k++) {
            int col = c4 * 4 + k;
            d_gsum[gph * M3 + col] = a[k];
            d_gsq[gph * M3 + col] = a[4 + k];
            d_gmax[gph * M3 + col] = a[8 + k];
            d_gmin[gph * M3 + col] = a[12 + k];
        }
    }
    if (tx == 0) d_gcnt[gph] = end - start;
}

// ---------------- bnh BN scale/shift from per-graph sums ----------------
__global__ void stats_pool_k(const float* __restrict__ gw, const float* __restrict__ gb) {
    int c = blockIdx.x * 128 + threadIdx.x;  // 0..383
    float ts = 0.f, tq = 0.f;
    for (int g2 = 0; g2 < NG; g2++) {
        ts += d_gsum[g2 * M3 + c];
        tq += d_gsq[g2 * M3 + c];
    }
    float mean = ts * (1.f / NN);
    float var = tq * (1.f / NN) - mean * mean;
    float sc = gw[c] * rsqrtf(var + EPSB);
    d_scH[c] = sc;
    d_shH[c] = gb[c] - mean * sc;
}

// ---------------- emit Hcat (parallel over graphs) ----------------
__global__ void emit_hcat_k() {
    int g2 = blockIdx.x;      // graph
    int c = threadIdx.x;      // 0..383
    float sc = d_scH[c], sh = d_shH[c];
    int cnt = d_gcnt[g2];
    float add = sc * d_gsum[g2 * M3 + c] + sh * (float)cnt;
    float avg = (cnt > 0) ? add / (float)cnt : 0.f;
    float mxv = 0.f;
    if (cnt > 0)
        mxv = (sc >= 0.f) ? fmaf(sc, d_gmax[g2 * M3 + c], sh)
                          : fmaf(sc, d_gmin[g2 * M3 + c], sh);
    d_Hcat[(size_t)g2 * CAT + c] = avg;
    d_Hcat[(size_t)g2 * CAT + 384 + c] = add;
    d_Hcat[(size_t)g2 * CAT + 768 + c] = mxv;
}

// ---------------- BN over graphs ----------------
__global__ void bn_graphs_k(const float* __restrict__ gw, const float* __restrict__ gb) {
    int c = blockIdx.x * blockDim.x + threadIdx.x;
    if (c >= CAT) return;
    float s = 0.f, ss = 0.f;
    for (int r = 0; r < NG; r++) { float v = d_Hcat[r * CAT + c]; s += v; ss += v * v; }
    float mean = s * (1.f / NG);
    float var = ss * (1.f / NG) - mean * mean;
    float sc = gw[c] * rsqrtf(var + EPSB);
    float sh = gb[c] - mean * sc;
    for (int r = 0; r < NG; r++) d_Hbn[r * CAT + c] = fmaf(d_Hcat[r * CAT + c], sc, sh);
}

// ---------------- small dense layer ----------------
__global__ void mlp_k(const float* __restrict__ A, int Kd,
                      const float* __restrict__ W, const float* __restrict__ bias,
                      float* __restrict__ out, int Od, int do_relu) {
    extern __shared__ float sA[];
    int g0 = blockIdx.y * 8;
    for (int idx = threadIdx.x; idx < 8 * Kd; idx += blockDim.x)
        sA[idx] = A[(size_t)(g0 + idx / Kd) * Kd + (idx % Kd)];
    __syncthreads();
    int o = blockIdx.x * blockDim.x + threadIdx.x;
    float bb = bias[o];
    float acc[8];
#pragma unroll
    for (int j = 0; j < 8; j++) acc[j] = bb;
    const float* wr = W + (size_t)o * Kd;
    for (int k = 0; k < Kd; k++) {
        float w = wr[k];
#pragma unroll
        for (int j = 0; j < 8; j++) acc[j] = fmaf(w, sA[j * Kd + k], acc[j]);
    }
#pragma unroll
    for (int j = 0; j < 8; j++) {
        float v = acc[j];
        if (do_relu) v = fmaxf(v, 0.f);
        out[(size_t)(g0 + j) * Od + o] = v;
    }
}

// ---------------- final layer + log_softmax ----------------
__global__ void final_k(const float* __restrict__ w3, const float* __restrict__ b3,
                        float* __restrict__ out) {
    int g = threadIdx.x;
    if (g >= NG) return;
    float l0 = b3[0], l1 = b3[1];
    const float* h = d_h2 + (size_t)g * 384;
    for (int k = 0; k < 384; k++) {
        float v = h[k];
        l0 = fmaf(v, w3[k], l0);
        l1 = fmaf(v, w3[384 + k], l1);
    }
    float m = fmaxf(l0, l1);
    float lse = m + logf(expf(l0 - m) + expf(l1 - m));
    out[g * 2 + 0] = l0 - lse;
    out[g * 2 + 1] = l1 - lse;
}

extern "C" void kernel_launch(void* const* d_in, const int* in_sizes, int n_in,
                              void* d_out, int out_size) {
    const float* x      = (const float*)d_in[0];
    const int*   ei     = (const int*)d_in[1];
    const int*   batch  = (const int*)d_in[2];
    const float* w_rel  = (const float*)d_in[4];
    const float* b_rel  = (const float*)d_in[5];
    const float* w_root = (const float*)d_in[6];
    const float* n0g    = (const float*)d_in[7];
    const float* n0b    = (const float*)d_in[8];
    const float* lin_w  = (const float*)d_in[9];
    const float* lin_b  = (const float*)d_in[10];
    const float* bnh_g  = (const float*)d_in[11];
    const float* bnh_b  = (const float*)d_in[12];
    const float* bno_g  = (const float*)d_in[13];
    const float* bno_b  = (const float*)d_in[14];
    const float* w1     = (const float*)d_in[15];
    const float* b1     = (const float*)d_in[16];
    const float* w2     = (const float*)d_in[17];
    const float* b2     = (const float*)d_in[18];
    const float* w3     = (const float*)d_in[19];
    const float* b3     = (const float*)d_in[20];
    float* out = (float*)d_out;
    const int* row = ei;
    const int* col = ei + NE;

    float *p_neigh, *p_Xr, *p_H1, *p_H2, *p_stX, *p_scX, *p_shX;
    float *p_Hbn, *p_h1, *p_h2, *p_xr, *p_wrelt, *p_wroott, *p_Hm;
    int *p_offc, *p_offr, *p_srcc, *p_srcr;
    cudaGetSymbolAddress((void**)&p_neigh, d_neigh);
    cudaGetSymbolAddress((void**)&p_Xr, d_Xr);
    cudaGetSymbolAddress((void**)&p_H1, d_H1);
    cudaGetSymbolAddress((void**)&p_H2, d_H2);
    cudaGetSymbolAddress((void**)&p_Hm, d_Hm);
    cudaGetSymbolAddress((void**)&p_stX, d_stX);
    cudaGetSymbolAddress((void**)&p_scX, d_scX);
    cudaGetSymbolAddress((void**)&p_shX, d_shX);
    cudaGetSymbolAddress((void**)&p_Hbn, d_Hbn);
    cudaGetSymbolAddress((void**)&p_h1, d_h1);
    cudaGetSymbolAddress((void**)&p_h2, d_h2);
    cudaGetSymbolAddress((void**)&p_xr, d_xr);
    cudaGetSymbolAddress((void**)&p_wrelt, d_wrelt);
    cudaGetSymbolAddress((void**)&p_wroott, d_wroott);
    cudaGetSymbolAddress((void**)&p_offc, d_offc);
    cudaGetSymbolAddress((void**)&p_offr, d_offr);
    cudaGetSymbolAddress((void**)&p_srcc, d_srcc);
    cudaGetSymbolAddress((void**)&p_srcr, d_srcr);

    cudaFuncSetAttribute(gemm_x_k, cudaFuncAttributeMaxDynamicSharedMemorySize, GSMEM);
    cudaFuncSetAttribute(gemm_hm_k, cudaFuncAttributeMaxDynamicSharedMemorySize, GSMEM);

    const int ROWBLK = (NN + 127) / 128;   // 391
    const int NODEBLK = (NN + 7) / 8;      // 6250

    // ---- CSR build + operand rounding ----
    init_k<<<(NN + 255) / 256, 256>>>();
    hist_k<<<(NE + 255) / 256, 256>>>(row, col);
    scan_k<<<2, SCAN_T>>>();
    fill_k<<<(NE + 255) / 256, 256>>>(row, col);
    round_copy_k<<<(NN * CDIM + 255) / 256, 256>>>(x, p_xr, NN * CDIM);
    round_copy_k<<<(CDIM * CDIM + 255) / 256, 256>>>(w_rel, p_wrelt, CDIM * CDIM);
    round_copy_k<<<(CDIM * CDIM + 255) / 256, 256>>>(w_root, p_wroott, CDIM * CDIM);
    // neigh[n] = sum (dst=col) of x[src]  (stored tf32-rounded)
    spmm_csr_k<<<NODEBLK, 256>>>(x, p_neigh, p_offc, p_srcc, nullptr, nullptr);
    // Xr = tf32( neigh @ w_rel^T + x @ w_root^T + b_rel )
    gemm_x_k<<<ROWBLK, 256, GSMEM>>>(b_rel);
    stats2_k<<<400, 256>>>(p_Xr, 128, p_stX, 125);
    finalize_bnX_k<<<1, 128>>>(n0g, n0b);
    lin_transform_k<<<M3, 128>>>(lin_w, lin_b);
    // H1 = A·BN(Xr) (affine fused, rounded); H2 = A·H1 (rounded)
    spmm_csr_k<<<NODEBLK, 256>>>(p_Xr, p_H1, p_offr, p_srcr, p_scX, p_shX);
    spmm_csr_k<<<NODEBLK, 256>>>(p_H1, p_H2, p_offr, p_srcr, nullptr, nullptr);
    // masked block-lower-triangular lin GEMM (BN folded into weights)
    gemm_hm_k<<<dim3(ROWBLK, 3), 256, GSMEM>>>();
    // single-read per-graph pooling; bnh BN stats from per-graph sums
    pool_raw_k<<<NG, 384>>>(batch);
    stats_pool_k<<<3, 128>>>(bnh_g, bnh_b);
    emit_hcat_k<<<NG, 384>>>();
    bn_graphs_k<<<CAT / 128, 128>>>(bno_g, bno_b);
    mlp_k<<<dim3(768 / 128, NG / 8), 128, 8 * 1152 * sizeof(float)>>>(
        p_Hbn, 1152, w1, b1, p_h1, 768, 1);
    mlp_k<<<dim3(384 / 128, NG / 8), 128, 8 * 768 * sizeof(float)>>>(
        p_h1, 768, w2, b2, p_h2, 384, 1);
    final_k<<<1, 128>>>(w3, b3, out);
}